// round 6
// baseline (speedup 1.0000x reference)
#include <cuda_runtime.h>
#include <math.h>
#include <stdint.h>

#define Bv   32
#define QL   32
#define DOCL 2048
#define Sv   64
#define Ev   300
#define Hv   256
#define G3   768    // 3*H
#define KP   304    // padded K for GEMM (19 tiles of 16)
#define WSTR 268    // smem row stride (floats)
#define CLS  8      // cluster size

// ---------------- scratch ----------------
__device__ float g_facts[Bv*Sv*Ev];
__device__ float g_xg_q[Bv*QL*G3];
__device__ float g_xg_f[Bv*Sv*G3];
__device__ float g_xg_b[Bv*Sv*G3];
__device__ float g_hf[Bv*Sv*Hv];
__device__ float g_hb[Bv*Sv*Hv];

// packed 2xfp32 FMA
#define FFMA2(acc, a, b) asm("fma.rn.f32x2 %0, %1, %2, %0;" : "+l"(acc) : "l"(a), "l"(b))
#define DUP2(d, s)       asm("mov.b64 %0, {%1, %1};" : "=l"(d) : "f"(s))

__device__ __forceinline__ float psum2(unsigned long long v) {
    float lo, hi;
    asm("mov.b64 {%0,%1}, %2;" : "=f"(lo), "=f"(hi) : "l"(v));
    return lo + hi;
}
__device__ __forceinline__ void unpack2(unsigned long long v, float& lo, float& hi) {
    asm("mov.b64 {%0,%1}, %2;" : "=f"(lo), "=f"(hi) : "l"(v));
}
__device__ __forceinline__ float fast_sigmoid(float x) {
    return 1.f / (1.f + __expf(-x));
}
__device__ __forceinline__ float fast_tanh(float x) {
    // 2*sigmoid(2x)-1; safe at +/-inf, rel err ~2^-21
    return 2.f / (1.f + __expf(-2.f * x)) - 1.f;
}

// ---------------- facts: ragged per-sentence mean pooling ----------------
__global__ void facts_kernel(const int* __restrict__ docs,
                             const int* __restrict__ slen,
                             const float* __restrict__ emb) {
    __shared__ int toks[DOCL];
    int bs = blockIdx.x;
    int b = bs >> 6, s = bs & 63;
    const int* sl = slen + b * Sv;
    int start = 0;
    for (int i = 0; i < s; i++) start += sl[i];
    int len = sl[s];
    if (len > DOCL - start) len = DOCL - start;
    const int* dp = docs + b * DOCL + start;
    for (int i = threadIdx.x; i < len; i += blockDim.x) toks[i] = dp[i];
    __syncthreads();
    int e = threadIdx.x;
    if (e < Ev) {
        float acc = 0.f;
        for (int i = 0; i < len; i++)
            acc += emb[(size_t)toks[i] * Ev + e];
        float d = (len > 0) ? (float)len : 1.0f;
        g_facts[(size_t)bs * Ev + e] = acc / d;
    }
}

// ---------------- merged xg GEMM: 5120 x 768 x 304 ----------------
__global__ __launch_bounds__(512, 1) void xg_gemm(
        const int* __restrict__ queries, const float* __restrict__ emb,
        const float* __restrict__ qwih, const float* __restrict__ fwih,
        const float* __restrict__ bwih,
        const float* __restrict__ qbih, const float* __restrict__ fbih,
        const float* __restrict__ bbih) {
    __shared__ float As[16][264];
    __shared__ float Bs[16][132];

    int m0 = blockIdx.y * 256, n0 = blockIdx.x * 128;
    int which = (m0 < 1024) ? 0 : ((m0 < 3072) ? 1 : 2);
    int mbase = (which == 0) ? 0 : (which == 1) ? 1024 : 3072;
    const float* wih = (which == 0) ? qwih : (which == 1) ? fwih : bwih;
    const float* bih = (which == 0) ? qbih : (which == 1) ? fbih : bbih;
    float* outb = ((which == 0) ? g_xg_q : (which == 1) ? g_xg_f : g_xg_b)
                  + (size_t)(m0 - mbase) * G3;

    int tid = threadIdx.x, tx = tid & 15, ty = tid >> 4;

    const float* asrc[2];
    int ac[2];
#pragma unroll
    for (int i = 0; i < 2; i++) {
        int idx = tid + i * 512;
        int r = idx >> 2;
        ac[i] = idx & 3;
        int m = m0 + r;
        asrc[i] = (which == 0) ? (emb + (size_t)queries[m] * Ev)
                               : (g_facts + (size_t)(m - mbase) * Ev);
    }
    int ar0 = (tid) >> 2, ar1 = (tid + 512) >> 2;
    int bn = tid >> 2, bkq = tid & 3;
    const float* brow = wih + (size_t)(n0 + bn) * Ev;

    unsigned long long acc[8][4];
#pragma unroll
    for (int i = 0; i < 8; i++)
#pragma unroll
        for (int j = 0; j < 4; j++) acc[i][j] = 0ull;

    for (int k0 = 0; k0 < KP; k0 += 16) {
#pragma unroll
        for (int i = 0; i < 2; i++) {
            int k = k0 + ac[i] * 4;
            float4 av = (k < Ev) ? *reinterpret_cast<const float4*>(asrc[i] + k)
                                 : make_float4(0.f, 0.f, 0.f, 0.f);
            int r = (i == 0) ? ar0 : ar1;
            As[ac[i]*4+0][r] = av.x; As[ac[i]*4+1][r] = av.y;
            As[ac[i]*4+2][r] = av.z; As[ac[i]*4+3][r] = av.w;
        }
        {
            int k = k0 + bkq * 4;
            float4 bv = (k < Ev) ? *reinterpret_cast<const float4*>(brow + k)
                                 : make_float4(0.f, 0.f, 0.f, 0.f);
            Bs[bkq*4+0][bn] = bv.x; Bs[bkq*4+1][bn] = bv.y;
            Bs[bkq*4+2][bn] = bv.z; Bs[bkq*4+3][bn] = bv.w;
        }
        __syncthreads();
#pragma unroll
        for (int k = 0; k < 16; k++) {
            float4 a0 = *reinterpret_cast<const float4*>(&As[k][ty * 8]);
            float4 a1 = *reinterpret_cast<const float4*>(&As[k][ty * 8 + 4]);
            ulonglong2 b01 = *reinterpret_cast<const ulonglong2*>(&Bs[k][tx * 8]);
            ulonglong2 b23 = *reinterpret_cast<const ulonglong2*>(&Bs[k][tx * 8 + 4]);
            float af[8] = {a0.x, a0.y, a0.z, a0.w, a1.x, a1.y, a1.z, a1.w};
#pragma unroll
            for (int i = 0; i < 8; i++) {
                unsigned long long ad; DUP2(ad, af[i]);
                FFMA2(acc[i][0], ad, b01.x);
                FFMA2(acc[i][1], ad, b01.y);
                FFMA2(acc[i][2], ad, b23.x);
                FFMA2(acc[i][3], ad, b23.y);
            }
        }
        __syncthreads();
    }
#pragma unroll
    for (int i = 0; i < 8; i++) {
        float* orow = outb + (size_t)(ty * 8 + i) * G3 + n0 + tx * 8;
#pragma unroll
        for (int jp = 0; jp < 4; jp++) {
            float lo, hi; unpack2(acc[i][jp], lo, hi);
            orow[2*jp]   = lo + bih[n0 + tx*8 + 2*jp];
            orow[2*jp+1] = hi + bih[n0 + tx*8 + 2*jp + 1];
        }
    }
}

// ---------------- GRU: 12 clusters x 8 CTAs, 512 threads, k-split ----------------
// thread: half = tid>>8 (k half), u = (tid>>3)&31 (unit in CTA slice), bl = tid&7 (batch)
extern "C" __global__ void __cluster_dims__(CLS, 1, 1) __launch_bounds__(512, 1)
gru_cluster(const int* __restrict__ qlen,
            const float* __restrict__ qwhh, const float* __restrict__ fwhh,
            const float* __restrict__ bwhh,
            const float* __restrict__ qbhh, const float* __restrict__ fbhh,
            const float* __restrict__ bbhh,
            float* __restrict__ d_out) {
    extern __shared__ float sm[];
    float* sw   = sm;                    // [96][WSTR] weight rows (gate*32+u)
    float* sh   = sm + 96 * WSTR;        // [2][8][WSTR] double-buffered h
    float* stgP = sm + 112 * WSTR;       // [256][3] half-1 partials
    float* stg2 = stgP + 768;            // [8][32] hnew tile

    int cid = blockIdx.x / CLS;
    int crank = blockIdx.x - cid * CLS;
    int gru = cid >> 2, bg = cid & 3;
    int tid = threadIdx.x;

    const float* whh = (gru == 0) ? qwhh : (gru == 1) ? fwhh : bwhh;
    const float* bhh = (gru == 0) ? qbhh : (gru == 1) ? fbhh : bbhh;
    const float* xg  = (gru == 0) ? g_xg_q : (gru == 1) ? g_xg_f : g_xg_b;
    float* hout = (gru == 1) ? g_hf : g_hb;
    int T = (gru == 0) ? QL : Sv;

    // load 96 weight rows (3 gates x 32 units), coalesced float4
    for (int i = tid; i < 96 * 64; i += 512) {
        int gi = i >> 6, k4 = i & 63;
        int g = gi >> 5, uu = gi & 31;
        float4 v = *reinterpret_cast<const float4*>(
            &whh[(size_t)((g << 8) + (crank << 5) + uu) * Hv + (k4 << 2)]);
        *reinterpret_cast<float4*>(&sw[gi * WSTR + (k4 << 2)]) = v;
    }
    for (int i = tid; i < 16 * WSTR; i += 512) sh[i] = 0.f;
    __syncthreads();
    asm volatile("barrier.cluster.arrive.aligned;" ::: "memory");
    asm volatile("barrier.cluster.wait.aligned;"   ::: "memory");

    int half = tid >> 8;
    int u  = (tid >> 3) & 31;
    int bl = tid & 7;
    int pi = tid & 255;              // (u<<3)|bl
    int ug = (crank << 5) + u;
    int b  = (bg << 3) + bl;
    float br = bhh[ug], bz = bhh[256 + ug], bn = bhh[512 + ug];
    int qm1 = (gru == 0) ? (qlen[b] - 1) : -2;
    const float* xgb = xg + (size_t)b * T * G3;

    const float* wr = sw + (size_t)(u)      * WSTR + (half << 7);
    const float* wz = sw + (size_t)(32 + u) * WSTR + (half << 7);
    const float* wn = sw + (size_t)(64 + u) * WSTR + (half << 7);

    uint32_t sh_u32;
    asm("{ .reg .u64 t; cvta.to.shared.u64 t, %1; cvt.u32.u64 %0, t; }"
        : "=r"(sh_u32) : "l"(sh));

    // broadcast assignment: 1 vector store per thread
    int rk  = tid >> 6;
    int rem = tid & 63;
    int bbl = rem >> 3, cc = rem & 7;
    uint32_t bc_off0 = (uint32_t)(bbl * WSTR + (crank << 5) + (cc << 2)) * 4u;

    for (int step = 0; step < T; step++) {
        int t = (gru == 2) ? (T - 1 - step) : step;
        int p = step & 1;
        const float* hbase = sh + (size_t)(p * 8 + bl) * WSTR;
        const float* hb = hbase + (half << 7);

        float ir = 0.f, iz = 0.f, in_ = 0.f, hold = 0.f;
        if (!half) {
            const float* xr = xgb + (size_t)t * G3;
            ir = xr[ug]; iz = xr[256 + ug]; in_ = xr[512 + ug];
            hold = hbase[ug];
        }

        unsigned long long a0 = 0, a1 = 0, c0 = 0, c1 = 0, e0 = 0, e1 = 0;
#pragma unroll
        for (int k4 = 0; k4 < 32; k4++) {
            ulonglong2 hv  = *reinterpret_cast<const ulonglong2*>(&hb[k4 << 2]);
            ulonglong2 wrv = *reinterpret_cast<const ulonglong2*>(&wr[k4 << 2]);
            ulonglong2 wzv = *reinterpret_cast<const ulonglong2*>(&wz[k4 << 2]);
            ulonglong2 wnv = *reinterpret_cast<const ulonglong2*>(&wn[k4 << 2]);
            FFMA2(a0, wrv.x, hv.x); FFMA2(a1, wrv.y, hv.y);
            FFMA2(c0, wzv.x, hv.x); FFMA2(c1, wzv.y, hv.y);
            FFMA2(e0, wnv.x, hv.x); FFMA2(e1, wnv.y, hv.y);
        }
        float pr = psum2(a0) + psum2(a1);
        float pz = psum2(c0) + psum2(c1);
        float pn = psum2(e0) + psum2(e1);

        if (half) {
            stgP[3 * pi]     = pr;
            stgP[3 * pi + 1] = pz;
            stgP[3 * pi + 2] = pn;
        }
        __syncthreads();

        if (!half) {
            float ghr = pr + stgP[3 * pi]     + br;
            float ghz = pz + stgP[3 * pi + 1] + bz;
            float ghn = pn + stgP[3 * pi + 2] + bn;
            float r = fast_sigmoid(ir + ghr);
            float z = fast_sigmoid(iz + ghz);
            float n = fast_tanh(in_ + r * ghn);
            float hnew = (1.f - z) * n + z * hold;
            stg2[(bl << 5) + u] = hnew;
            if (gru == 0 && t == qm1) d_out[(size_t)b * Hv + ug] = hnew;
        }
        __syncthreads();

        // cluster broadcast: 512 x st.shared::cluster.v4 (1/thread)
        {
            float4 v = *reinterpret_cast<const float4*>(&stg2[(bbl << 5) + (cc << 2)]);
            uint32_t loff = sh_u32 + (uint32_t)(((1 - p) * 8) * WSTR) * 4u + bc_off0;
            uint32_t raddr;
            asm("mapa.shared::cluster.u32 %0, %1, %2;" : "=r"(raddr) : "r"(loff), "r"(rk));
            asm volatile("st.shared::cluster.v4.f32 [%0], {%1,%2,%3,%4};"
                         :: "r"(raddr), "f"(v.x), "f"(v.y), "f"(v.z), "f"(v.w) : "memory");
        }
        asm volatile("barrier.cluster.arrive.aligned;" ::: "memory");
        // overlap coalesced gmem output with barrier
        if (gru != 0 && tid < 64) {
            float4 v = *reinterpret_cast<const float4*>(&stg2[(bbl << 5) + (cc << 2)]);
            *reinterpret_cast<float4*>(
                &hout[((size_t)((bg << 3) + bbl) * Sv + t) * Hv + (crank << 5) + (cc << 2)]) = v;
        }
        asm volatile("barrier.cluster.wait.aligned;" ::: "memory");
    }
}

// ---------------- combine: f_out = hf + hb, plus num_facts ----------------
__global__ void combine_kernel(const int* __restrict__ slen, float* __restrict__ d_out) {
    int idx = blockIdx.x * blockDim.x + threadIdx.x;
    const int NF4 = (Bv * Sv * Hv) / 4;
    if (idx < NF4) {
        const float4* hf4 = reinterpret_cast<const float4*>(g_hf);
        const float4* hb4 = reinterpret_cast<const float4*>(g_hb);
        float4 a = hf4[idx], c = hb4[idx];
        float4 o = make_float4(a.x + c.x, a.y + c.y, a.z + c.z, a.w + c.w);
        reinterpret_cast<float4*>(d_out + Bv * Hv)[idx] = o;
    }
    if (idx < Bv) {
        int c = 0;
        const int* sl = slen + idx * Sv;
        for (int s = 0; s < Sv; s++) c += (sl[s] > 0) ? 1 : 0;
        d_out[Bv * Hv + Bv * Sv * Hv + idx] = (float)c;
    }
}

// ---------------- launch ----------------
extern "C" void kernel_launch(void* const* d_in, const int* in_sizes, int n_in,
                              void* d_out, int out_size) {
    const int*   queries = (const int*)d_in[0];
    const int*   qlen    = (const int*)d_in[1];
    const int*   docs    = (const int*)d_in[2];
    const int*   slen    = (const int*)d_in[3];
    const float* emb     = (const float*)d_in[4];
    const float* q_wih   = (const float*)d_in[5];
    const float* q_whh   = (const float*)d_in[6];
    const float* q_bih   = (const float*)d_in[7];
    const float* q_bhh   = (const float*)d_in[8];
    const float* f_wih   = (const float*)d_in[9];
    const float* f_whh   = (const float*)d_in[10];
    const float* f_bih   = (const float*)d_in[11];
    const float* f_bhh   = (const float*)d_in[12];
    const float* b_wih   = (const float*)d_in[13];
    const float* b_whh   = (const float*)d_in[14];
    const float* b_bih   = (const float*)d_in[15];
    const float* b_bhh   = (const float*)d_in[16];
    float* out = (float*)d_out;

    const int GRU_SMEM = (112 * WSTR + 768 + 256) * 4;   // 124160 B
    cudaFuncSetAttribute(gru_cluster, cudaFuncAttributeMaxDynamicSharedMemorySize, GRU_SMEM);

    facts_kernel<<<Bv * Sv, 320>>>(docs, slen, emb);

    dim3 gg(6, 20);   // 120 CTAs, single wave
    xg_gemm<<<gg, 512>>>(queries, emb, q_wih, f_wih, b_wih, q_bih, f_bih, b_bih);

    gru_cluster<<<96, 512, GRU_SMEM>>>(qlen, q_whh, f_whh, b_whh,
                                       q_bhh, f_bhh, b_bhh, out);

    combine_kernel<<<(Bv * Sv * Hv / 4 + 255) / 256, 256>>>(slen, out);
}

// round 7
// speedup vs baseline: 1.2072x; 1.2072x over previous
#include <cuda_runtime.h>
#include <math.h>
#include <stdint.h>

#define Bv   32
#define QL   32
#define DOCL 2048
#define Sv   64
#define Ev   300
#define Hv   256
#define G3   768    // 3*H
#define KP   304    // padded K for GEMM
#define CLS  8      // cluster size

// ---------------- scratch ----------------
__device__ float g_facts[Bv*Sv*Ev];
__device__ float g_xg_q[Bv*QL*G3];
__device__ float g_xg_f[Bv*Sv*G3];
__device__ float g_xg_b[Bv*Sv*G3];
__device__ float g_hf[Bv*Sv*Hv];
__device__ float g_hb[Bv*Sv*Hv];

// packed 2xfp32 ops
#define FFMA2(acc, a, b) asm("fma.rn.f32x2 %0, %1, %2, %0;" : "+l"(acc) : "l"(a), "l"(b))
#define ADDF2(o, a, b)   asm("add.rn.f32x2 %0, %1, %2;" : "=l"(o) : "l"(a), "l"(b))
#define DUP2(d, s)       asm("mov.b64 %0, {%1, %1};" : "=l"(d) : "f"(s))

__device__ __forceinline__ float psum2(unsigned long long v) {
    float lo, hi;
    asm("mov.b64 {%0,%1}, %2;" : "=f"(lo), "=f"(hi) : "l"(v));
    return lo + hi;
}
__device__ __forceinline__ void unpack2(unsigned long long v, float& lo, float& hi) {
    asm("mov.b64 {%0,%1}, %2;" : "=f"(lo), "=f"(hi) : "l"(v));
}
__device__ __forceinline__ float fast_sigmoid(float x) {
    return 1.f / (1.f + __expf(-x));
}
__device__ __forceinline__ float fast_tanh(float x) {
    return 2.f / (1.f + __expf(-2.f * x)) - 1.f;
}

// ---------------- facts: ragged per-sentence mean pooling ----------------
__global__ void facts_kernel(const int* __restrict__ docs,
                             const int* __restrict__ slen,
                             const float* __restrict__ emb) {
    __shared__ int toks[DOCL];
    int bs = blockIdx.x;
    int b = bs >> 6, s = bs & 63;
    const int* sl = slen + b * Sv;
    int start = 0;
    for (int i = 0; i < s; i++) start += sl[i];
    int len = sl[s];
    if (len > DOCL - start) len = DOCL - start;
    const int* dp = docs + b * DOCL + start;
    for (int i = threadIdx.x; i < len; i += blockDim.x) toks[i] = dp[i];
    __syncthreads();
    int e = threadIdx.x;
    if (e < Ev) {
        float acc = 0.f;
        for (int i = 0; i < len; i++)
            acc += emb[(size_t)toks[i] * Ev + e];
        float d = (len > 0) ? (float)len : 1.0f;
        g_facts[(size_t)bs * Ev + e] = acc / d;
    }
}

// ---------------- merged xg GEMM: 5120 x 768 x 304 (unchanged) ----------------
__global__ __launch_bounds__(512, 1) void xg_gemm(
        const int* __restrict__ queries, const float* __restrict__ emb,
        const float* __restrict__ qwih, const float* __restrict__ fwih,
        const float* __restrict__ bwih,
        const float* __restrict__ qbih, const float* __restrict__ fbih,
        const float* __restrict__ bbih) {
    __shared__ float As[16][264];
    __shared__ float Bs[16][132];

    int m0 = blockIdx.y * 256, n0 = blockIdx.x * 128;
    int which = (m0 < 1024) ? 0 : ((m0 < 3072) ? 1 : 2);
    int mbase = (which == 0) ? 0 : (which == 1) ? 1024 : 3072;
    const float* wih = (which == 0) ? qwih : (which == 1) ? fwih : bwih;
    const float* bih = (which == 0) ? qbih : (which == 1) ? fbih : bbih;
    float* outb = ((which == 0) ? g_xg_q : (which == 1) ? g_xg_f : g_xg_b)
                  + (size_t)(m0 - mbase) * G3;

    int tid = threadIdx.x, tx = tid & 15, ty = tid >> 4;

    const float* asrc[2];
    int ac[2];
#pragma unroll
    for (int i = 0; i < 2; i++) {
        int idx = tid + i * 512;
        int r = idx >> 2;
        ac[i] = idx & 3;
        int m = m0 + r;
        asrc[i] = (which == 0) ? (emb + (size_t)queries[m] * Ev)
                               : (g_facts + (size_t)(m - mbase) * Ev);
    }
    int ar0 = (tid) >> 2, ar1 = (tid + 512) >> 2;
    int bn = tid >> 2, bkq = tid & 3;
    const float* brow = wih + (size_t)(n0 + bn) * Ev;

    unsigned long long acc[8][4];
#pragma unroll
    for (int i = 0; i < 8; i++)
#pragma unroll
        for (int j = 0; j < 4; j++) acc[i][j] = 0ull;

    for (int k0 = 0; k0 < KP; k0 += 16) {
#pragma unroll
        for (int i = 0; i < 2; i++) {
            int k = k0 + ac[i] * 4;
            float4 av = (k < Ev) ? *reinterpret_cast<const float4*>(asrc[i] + k)
                                 : make_float4(0.f, 0.f, 0.f, 0.f);
            int r = (i == 0) ? ar0 : ar1;
            As[ac[i]*4+0][r] = av.x; As[ac[i]*4+1][r] = av.y;
            As[ac[i]*4+2][r] = av.z; As[ac[i]*4+3][r] = av.w;
        }
        {
            int k = k0 + bkq * 4;
            float4 bv = (k < Ev) ? *reinterpret_cast<const float4*>(brow + k)
                                 : make_float4(0.f, 0.f, 0.f, 0.f);
            Bs[bkq*4+0][bn] = bv.x; Bs[bkq*4+1][bn] = bv.y;
            Bs[bkq*4+2][bn] = bv.z; Bs[bkq*4+3][bn] = bv.w;
        }
        __syncthreads();
#pragma unroll
        for (int k = 0; k < 16; k++) {
            float4 a0 = *reinterpret_cast<const float4*>(&As[k][ty * 8]);
            float4 a1 = *reinterpret_cast<const float4*>(&As[k][ty * 8 + 4]);
            ulonglong2 b01 = *reinterpret_cast<const ulonglong2*>(&Bs[k][tx * 8]);
            ulonglong2 b23 = *reinterpret_cast<const ulonglong2*>(&Bs[k][tx * 8 + 4]);
            float af[8] = {a0.x, a0.y, a0.z, a0.w, a1.x, a1.y, a1.z, a1.w};
#pragma unroll
            for (int i = 0; i < 8; i++) {
                unsigned long long ad; DUP2(ad, af[i]);
                FFMA2(acc[i][0], ad, b01.x);
                FFMA2(acc[i][1], ad, b01.y);
                FFMA2(acc[i][2], ad, b23.x);
                FFMA2(acc[i][3], ad, b23.y);
            }
        }
        __syncthreads();
    }
#pragma unroll
    for (int i = 0; i < 8; i++) {
        float* orow = outb + (size_t)(ty * 8 + i) * G3 + n0 + tx * 8;
#pragma unroll
        for (int jp = 0; jp < 4; jp++) {
            float lo, hi; unpack2(acc[i][jp], lo, hi);
            orow[2*jp]   = lo + bih[n0 + tx*8 + 2*jp];
            orow[2*jp+1] = hi + bih[n0 + tx*8 + 2*jp + 1];
        }
    }
}

// ---------------- GRU: weight-amortized, batch-packed f32x2 ----------------
// 12 clusters x 8 CTAs x 512 threads.
// Dot role:   ud = tid&31 (unit), kq = tid>>5 (k-chunk of 16); all 8 batches in f32x2 pairs.
// Reduce role: tid<384: u=tid/12, gbp=tid%12, sum 16 kq partials.
// Gate role:  tid<256: u=tid>>3, bl=tid&7.
// smem (floats): swp[24576] | shT[2][256][8] | red[32*205 u64] | rsum[384 u64] | stg[256]
#define RED_USTR 205
#define RED_GSTR 17
extern "C" __global__ void __cluster_dims__(CLS, 1, 1) __launch_bounds__(512, 1)
gru_cluster(const int* __restrict__ qlen,
            const float* __restrict__ qwhh, const float* __restrict__ fwhh,
            const float* __restrict__ bwhh,
            const float* __restrict__ qbhh, const float* __restrict__ fbhh,
            const float* __restrict__ bbhh,
            float* __restrict__ d_out) {
    extern __shared__ float sm[];
    float* swp = sm;                                         // 24576 floats
    float* shT = sm + 24576;                                 // 4096 floats
    unsigned long long* redv = (unsigned long long*)(sm + 24576 + 4096);  // 6560 u64
    unsigned long long* rsum = redv + 32 * RED_USTR;         // 384 u64
    float* stg = (float*)(rsum + 384);                       // 256 floats

    int cid = blockIdx.x / CLS;
    int crank = blockIdx.x - cid * CLS;
    int gru = cid >> 2, bg = cid & 3;
    int tid = threadIdx.x;

    const float* whh = (gru == 0) ? qwhh : (gru == 1) ? fwhh : bwhh;
    const float* bhh = (gru == 0) ? qbhh : (gru == 1) ? fbhh : bbhh;
    const float* xg  = (gru == 0) ? g_xg_q : (gru == 1) ? g_xg_f : g_xg_b;
    float* hout = (gru == 1) ? g_hf : g_hb;
    int T = (gru == 0) ? QL : Sv;

    // ---- init: repack weights [kq][g][j4][u][4], zero both h buffers ----
    for (int i = tid; i < 96 * 64; i += 512) {
        int gi = i >> 6, k4 = i & 63;
        int g = gi >> 5, u = gi & 31;
        float4 v = *reinterpret_cast<const float4*>(
            &whh[(size_t)((g << 8) + (crank << 5) + u) * Hv + (k4 << 2)]);
        int kq = k4 >> 2, j4 = k4 & 3;
        *reinterpret_cast<float4*>(&swp[(((kq * 3 + g) << 2) + j4) * 128 + (u << 2)]) = v;
    }
    for (int i = tid; i < 4096; i += 512) shT[i] = 0.f;
    __syncthreads();
    asm volatile("barrier.cluster.arrive.aligned;" ::: "memory");
    asm volatile("barrier.cluster.wait.aligned;"   ::: "memory");

    // dot role
    int ud = tid & 31, kq = tid >> 5;
    // gate role
    int ugate = tid >> 3, blg = tid & 7;
    int ugx = (crank << 5) + ugate;
    int bgl = (bg << 3) + blg;
    float br = 0.f, bz = 0.f, bn2 = 0.f;
    int qm1 = -2;
    const float* xgb = nullptr;
    if (tid < 256) {
        br = bhh[ugx]; bz = bhh[256 + ugx]; bn2 = bhh[512 + ugx];
        if (gru == 0) qm1 = qlen[bgl] - 1;
        xgb = xg + (size_t)bgl * T * G3;
    }
    // broadcast role
    int rk = tid >> 6, rem = tid & 63;

    uint32_t shT_u32;
    asm("{ .reg .u64 t; cvta.to.shared.u64 t, %1; cvt.u32.u64 %0, t; }"
        : "=r"(shT_u32) : "l"(shT));

    int redbase_st = ud * RED_USTR + kq;           // + (g*4+bp)*RED_GSTR
    int redbase_ld = (tid / 12) * RED_USTR + (tid % 12) * RED_GSTR;

    for (int step = 0; step < T; step++) {
        int t = (gru == 2) ? (T - 1 - step) : step;
        int p = step & 1;

        // gate-role prefetch (LDG latency hides under the dot phase)
        float ir = 0.f, iz = 0.f, in_ = 0.f, hold = 0.f;
        if (tid < 256) {
            const float* xr = xgb + (size_t)t * G3;
            ir = xr[ugx]; iz = xr[256 + ugx]; in_ = xr[512 + ugx];
            hold = shT[((p << 8) + ugx) * 8 + blg];
        }

        // ---- dot: 3 gates x 16 k x 8 batches per thread ----
        unsigned long long acc[3][4];
#pragma unroll
        for (int g = 0; g < 3; g++)
#pragma unroll
            for (int bp = 0; bp < 4; bp++) acc[g][bp] = 0ull;

        const float* hT = shT + ((p << 8) + (kq << 4)) * 8;
#pragma unroll
        for (int j4 = 0; j4 < 4; j4++) {
            ulonglong2 h01[4], h45[4];
#pragma unroll
            for (int kk = 0; kk < 4; kk++) {
                const ulonglong2* hr = reinterpret_cast<const ulonglong2*>(
                    hT + ((j4 << 2) + kk) * 8);
                h01[kk] = hr[0];
                h45[kk] = hr[1];
            }
#pragma unroll
            for (int g = 0; g < 3; g++) {
                float4 wv = *reinterpret_cast<const float4*>(
                    &swp[(((kq * 3 + g) << 2) + j4) * 128 + (ud << 2)]);
                float wf[4] = {wv.x, wv.y, wv.z, wv.w};
#pragma unroll
                for (int kk = 0; kk < 4; kk++) {
                    unsigned long long wd; DUP2(wd, wf[kk]);
                    FFMA2(acc[g][0], wd, h01[kk].x);
                    FFMA2(acc[g][1], wd, h01[kk].y);
                    FFMA2(acc[g][2], wd, h45[kk].x);
                    FFMA2(acc[g][3], wd, h45[kk].y);
                }
            }
        }
        // store partials (bank-tuned layout)
#pragma unroll
        for (int g = 0; g < 3; g++)
#pragma unroll
            for (int bp = 0; bp < 4; bp++)
                redv[redbase_st + ((g << 2) + bp) * RED_GSTR] = acc[g][bp];
        __syncthreads();

        // ---- reduce over 16 kq ----
        if (tid < 384) {
            const unsigned long long* rp = redv + redbase_ld;
            unsigned long long s0 = rp[0], s1 = rp[1], s2 = rp[2], s3 = rp[3];
            ADDF2(s0, s0, rp[4]);  ADDF2(s1, s1, rp[5]);
            ADDF2(s2, s2, rp[6]);  ADDF2(s3, s3, rp[7]);
            ADDF2(s0, s0, rp[8]);  ADDF2(s1, s1, rp[9]);
            ADDF2(s2, s2, rp[10]); ADDF2(s3, s3, rp[11]);
            ADDF2(s0, s0, rp[12]); ADDF2(s1, s1, rp[13]);
            ADDF2(s2, s2, rp[14]); ADDF2(s3, s3, rp[15]);
            ADDF2(s0, s0, s1); ADDF2(s2, s2, s3);
            ADDF2(s0, s0, s2);
            rsum[tid] = s0;
        }
        __syncthreads();

        // ---- gates ----
        if (tid < 256) {
            int bp = blg >> 1, sel = blg & 1;
            float lo, hi;
            unpack2(rsum[ugate * 12 + 0 * 4 + bp], lo, hi);
            float ghr = (sel ? hi : lo) + br;
            unpack2(rsum[ugate * 12 + 1 * 4 + bp], lo, hi);
            float ghz = (sel ? hi : lo) + bz;
            unpack2(rsum[ugate * 12 + 2 * 4 + bp], lo, hi);
            float ghn = (sel ? hi : lo) + bn2;

            float r = fast_sigmoid(ir + ghr);
            float z = fast_sigmoid(iz + ghz);
            float n = fast_tanh(in_ + r * ghn);
            float hnew = (1.f - z) * n + z * hold;
            stg[tid] = hnew;
            if (gru == 0) {
                if (t == qm1) d_out[(size_t)bgl * Hv + ugx] = hnew;
            } else {
                hout[((size_t)bgl * Sv + t) * Hv + ugx] = hnew;
            }
        }
        __syncthreads();

        // ---- cluster broadcast: 1 v4 per thread into peers' shT[1-p] slice ----
        {
            float4 v = *reinterpret_cast<const float4*>(&stg[rem << 2]);
            uint32_t loff = shT_u32 +
                (uint32_t)((((1 - p) << 8) + (crank << 5)) * 8 + (rem << 2)) * 4u;
            uint32_t raddr;
            asm("mapa.shared::cluster.u32 %0, %1, %2;" : "=r"(raddr) : "r"(loff), "r"(rk));
            asm volatile("st.shared::cluster.v4.f32 [%0], {%1,%2,%3,%4};"
                         :: "r"(raddr), "f"(v.x), "f"(v.y), "f"(v.z), "f"(v.w) : "memory");
        }
        asm volatile("barrier.cluster.arrive.aligned;" ::: "memory");
        asm volatile("barrier.cluster.wait.aligned;"   ::: "memory");
    }
}

// ---------------- combine: f_out = hf + hb, plus num_facts ----------------
__global__ void combine_kernel(const int* __restrict__ slen, float* __restrict__ d_out) {
    int idx = blockIdx.x * blockDim.x + threadIdx.x;
    const int NF4 = (Bv * Sv * Hv) / 4;
    if (idx < NF4) {
        const float4* hf4 = reinterpret_cast<const float4*>(g_hf);
        const float4* hb4 = reinterpret_cast<const float4*>(g_hb);
        float4 a = hf4[idx], c = hb4[idx];
        float4 o = make_float4(a.x + c.x, a.y + c.y, a.z + c.z, a.w + c.w);
        reinterpret_cast<float4*>(d_out + Bv * Hv)[idx] = o;
    }
    if (idx < Bv) {
        int c = 0;
        const int* sl = slen + idx * Sv;
        for (int s = 0; s < Sv; s++) c += (sl[s] > 0) ? 1 : 0;
        d_out[Bv * Hv + Bv * Sv * Hv + idx] = (float)c;
    }
}

// ---------------- launch ----------------
extern "C" void kernel_launch(void* const* d_in, const int* in_sizes, int n_in,
                              void* d_out, int out_size) {
    const int*   queries = (const int*)d_in[0];
    const int*   qlen    = (const int*)d_in[1];
    const int*   docs    = (const int*)d_in[2];
    const int*   slen    = (const int*)d_in[3];
    const float* emb     = (const float*)d_in[4];
    const float* q_wih   = (const float*)d_in[5];
    const float* q_whh   = (const float*)d_in[6];
    const float* q_bih   = (const float*)d_in[7];
    const float* q_bhh   = (const float*)d_in[8];
    const float* f_wih   = (const float*)d_in[9];
    const float* f_whh   = (const float*)d_in[10];
    const float* f_bih   = (const float*)d_in[11];
    const float* f_bhh   = (const float*)d_in[12];
    const float* b_wih   = (const float*)d_in[13];
    const float* b_whh   = (const float*)d_in[14];
    const float* b_bih   = (const float*)d_in[15];
    const float* b_bhh   = (const float*)d_in[16];
    float* out = (float*)d_out;

    // floats: swp 24576 + shT 4096 + red 13120 + rsum 768 + stg 256
    const int GRU_SMEM = (24576 + 4096 + 32 * RED_USTR * 2 + 384 * 2 + 256) * 4;
    cudaFuncSetAttribute(gru_cluster, cudaFuncAttributeMaxDynamicSharedMemorySize, GRU_SMEM);

    facts_kernel<<<Bv * Sv, 320>>>(docs, slen, emb);

    dim3 gg(6, 20);
    xg_gemm<<<gg, 512>>>(queries, emb, q_wih, f_wih, b_wih, q_bih, f_bih, b_bih);

    gru_cluster<<<96, 512, GRU_SMEM>>>(qlen, q_whh, f_whh, b_whh,
                                       q_bhh, f_bhh, b_bhh, out);

    combine_kernel<<<(Bv * Sv * Hv / 4 + 255) / 256, 256>>>(slen, out);
}

// round 8
// speedup vs baseline: 1.3290x; 1.1009x over previous
#include <cuda_runtime.h>
#include <math.h>
#include <stdint.h>

#define Bv   32
#define QL   32
#define DOCL 2048
#define Sv   64
#define Ev   300
#define Hv   256
#define G3   768    // 3*H
#define KP   304    // padded K for GEMM
#define CLS  8      // cluster size

// ---------------- scratch ----------------
__device__ float g_facts[Bv*Sv*Ev];
__device__ float g_xg_q[Bv*QL*G3];
__device__ float g_xg_f[Bv*Sv*G3];
__device__ float g_xg_b[Bv*Sv*G3];
__device__ float g_hf[Bv*Sv*Hv];
__device__ float g_hb[Bv*Sv*Hv];

// packed 2xfp32 ops
#define FFMA2(acc, a, b) asm("fma.rn.f32x2 %0, %1, %2, %0;" : "+l"(acc) : "l"(a), "l"(b))
#define ADDF2(o, a, b)   asm("add.rn.f32x2 %0, %1, %2;" : "=l"(o) : "l"(a), "l"(b))
#define DUP2(d, s)       asm("mov.b64 %0, {%1, %1};" : "=l"(d) : "f"(s))

__device__ __forceinline__ float psum2(unsigned long long v) {
    float lo, hi;
    asm("mov.b64 {%0,%1}, %2;" : "=f"(lo), "=f"(hi) : "l"(v));
    return lo + hi;
}
__device__ __forceinline__ void unpack2(unsigned long long v, float& lo, float& hi) {
    asm("mov.b64 {%0,%1}, %2;" : "=f"(lo), "=f"(hi) : "l"(v));
}
__device__ __forceinline__ float fast_sigmoid(float x) {
    return 1.f / (1.f + __expf(-x));
}
__device__ __forceinline__ float fast_tanh(float x) {
    return 2.f / (1.f + __expf(-2.f * x)) - 1.f;
}
__device__ __forceinline__ void mbar_wait_cluster(uint32_t mbar, uint32_t parity) {
    asm volatile(
        "{\n\t"
        ".reg .pred P;\n\t"
        "MWL_%=:\n\t"
        "mbarrier.try_wait.parity.acquire.cluster.shared::cta.b64 P, [%0], %1, 0x989680;\n\t"
        "@!P bra MWL_%=;\n\t"
        "}" :: "r"(mbar), "r"(parity) : "memory");
}

// ---------------- facts: ragged per-sentence mean pooling ----------------
__global__ void facts_kernel(const int* __restrict__ docs,
                             const int* __restrict__ slen,
                             const float* __restrict__ emb) {
    __shared__ int toks[DOCL];
    int bs = blockIdx.x;
    int b = bs >> 6, s = bs & 63;
    const int* sl = slen + b * Sv;
    int start = 0;
    for (int i = 0; i < s; i++) start += sl[i];
    int len = sl[s];
    if (len > DOCL - start) len = DOCL - start;
    const int* dp = docs + b * DOCL + start;
    for (int i = threadIdx.x; i < len; i += blockDim.x) toks[i] = dp[i];
    __syncthreads();
    int e = threadIdx.x;
    if (e < Ev) {
        float acc = 0.f;
        for (int i = 0; i < len; i++)
            acc += emb[(size_t)toks[i] * Ev + e];
        float d = (len > 0) ? (float)len : 1.0f;
        g_facts[(size_t)bs * Ev + e] = acc / d;
    }
}

// ---------------- merged xg GEMM: 5120 x 768 x 304 (unchanged) ----------------
__global__ __launch_bounds__(512, 1) void xg_gemm(
        const int* __restrict__ queries, const float* __restrict__ emb,
        const float* __restrict__ qwih, const float* __restrict__ fwih,
        const float* __restrict__ bwih,
        const float* __restrict__ qbih, const float* __restrict__ fbih,
        const float* __restrict__ bbih) {
    __shared__ float As[16][264];
    __shared__ float Bs[16][132];

    int m0 = blockIdx.y * 256, n0 = blockIdx.x * 128;
    int which = (m0 < 1024) ? 0 : ((m0 < 3072) ? 1 : 2);
    int mbase = (which == 0) ? 0 : (which == 1) ? 1024 : 3072;
    const float* wih = (which == 0) ? qwih : (which == 1) ? fwih : bwih;
    const float* bih = (which == 0) ? qbih : (which == 1) ? fbih : bbih;
    float* outb = ((which == 0) ? g_xg_q : (which == 1) ? g_xg_f : g_xg_b)
                  + (size_t)(m0 - mbase) * G3;

    int tid = threadIdx.x, tx = tid & 15, ty = tid >> 4;

    const float* asrc[2];
    int ac[2];
#pragma unroll
    for (int i = 0; i < 2; i++) {
        int idx = tid + i * 512;
        int r = idx >> 2;
        ac[i] = idx & 3;
        int m = m0 + r;
        asrc[i] = (which == 0) ? (emb + (size_t)queries[m] * Ev)
                               : (g_facts + (size_t)(m - mbase) * Ev);
    }
    int ar0 = (tid) >> 2, ar1 = (tid + 512) >> 2;
    int bn = tid >> 2, bkq = tid & 3;
    const float* brow = wih + (size_t)(n0 + bn) * Ev;

    unsigned long long acc[8][4];
#pragma unroll
    for (int i = 0; i < 8; i++)
#pragma unroll
        for (int j = 0; j < 4; j++) acc[i][j] = 0ull;

    for (int k0 = 0; k0 < KP; k0 += 16) {
#pragma unroll
        for (int i = 0; i < 2; i++) {
            int k = k0 + ac[i] * 4;
            float4 av = (k < Ev) ? *reinterpret_cast<const float4*>(asrc[i] + k)
                                 : make_float4(0.f, 0.f, 0.f, 0.f);
            int r = (i == 0) ? ar0 : ar1;
            As[ac[i]*4+0][r] = av.x; As[ac[i]*4+1][r] = av.y;
            As[ac[i]*4+2][r] = av.z; As[ac[i]*4+3][r] = av.w;
        }
        {
            int k = k0 + bkq * 4;
            float4 bv = (k < Ev) ? *reinterpret_cast<const float4*>(brow + k)
                                 : make_float4(0.f, 0.f, 0.f, 0.f);
            Bs[bkq*4+0][bn] = bv.x; Bs[bkq*4+1][bn] = bv.y;
            Bs[bkq*4+2][bn] = bv.z; Bs[bkq*4+3][bn] = bv.w;
        }
        __syncthreads();
#pragma unroll
        for (int k = 0; k < 16; k++) {
            float4 a0 = *reinterpret_cast<const float4*>(&As[k][ty * 8]);
            float4 a1 = *reinterpret_cast<const float4*>(&As[k][ty * 8 + 4]);
            ulonglong2 b01 = *reinterpret_cast<const ulonglong2*>(&Bs[k][tx * 8]);
            ulonglong2 b23 = *reinterpret_cast<const ulonglong2*>(&Bs[k][tx * 8 + 4]);
            float af[8] = {a0.x, a0.y, a0.z, a0.w, a1.x, a1.y, a1.z, a1.w};
#pragma unroll
            for (int i = 0; i < 8; i++) {
                unsigned long long ad; DUP2(ad, af[i]);
                FFMA2(acc[i][0], ad, b01.x);
                FFMA2(acc[i][1], ad, b01.y);
                FFMA2(acc[i][2], ad, b23.x);
                FFMA2(acc[i][3], ad, b23.y);
            }
        }
        __syncthreads();
    }
#pragma unroll
    for (int i = 0; i < 8; i++) {
        float* orow = outb + (size_t)(ty * 8 + i) * G3 + n0 + tx * 8;
#pragma unroll
        for (int jp = 0; jp < 4; jp++) {
            float lo, hi; unpack2(acc[i][jp], lo, hi);
            orow[2*jp]   = lo + bih[n0 + tx*8 + 2*jp];
            orow[2*jp+1] = hi + bih[n0 + tx*8 + 2*jp + 1];
        }
    }
}

// ---------------- GRU: weight-amortized, mbarrier-tx synced ----------------
// 12 clusters x 8 CTAs x 512 threads.
// Dot role:   ud = tid&31 (unit), kq = tid>>5 (k-chunk of 16); 8 batches in f32x2 pairs.
// Reduce role: tid<384. Gate role: tid<256 (u=tid>>3, bl=tid&7).
#define RED_USTR 205
#define RED_GSTR 17
extern "C" __global__ void __cluster_dims__(CLS, 1, 1) __launch_bounds__(512, 1)
gru_cluster(const int* __restrict__ qlen,
            const float* __restrict__ qwhh, const float* __restrict__ fwhh,
            const float* __restrict__ bwhh,
            const float* __restrict__ qbhh, const float* __restrict__ fbhh,
            const float* __restrict__ bbhh,
            float* __restrict__ d_out) {
    extern __shared__ float sm[];
    float* swp = sm;                                         // 24576 floats
    float* shT = sm + 24576;                                 // 4096 floats [2][256][8]
    unsigned long long* redv = (unsigned long long*)(sm + 24576 + 4096);
    unsigned long long* rsum = redv + 32 * RED_USTR;         // 384 u64
    float* stg = (float*)(rsum + 384);                       // [2][256] double-buffered
    unsigned long long* mbar = (unsigned long long*)(stg + 512);

    int cid = blockIdx.x / CLS;
    int crank = blockIdx.x - cid * CLS;
    int gru = cid >> 2, bg = cid & 3;
    int tid = threadIdx.x;

    const float* whh = (gru == 0) ? qwhh : (gru == 1) ? fwhh : bwhh;
    const float* bhh = (gru == 0) ? qbhh : (gru == 1) ? fbhh : bbhh;
    const float* xg  = (gru == 0) ? g_xg_q : (gru == 1) ? g_xg_f : g_xg_b;
    float* hout = (gru == 1) ? g_hf : g_hb;
    int T = (gru == 0) ? QL : Sv;

    // ---- init: repack weights [kq][g][j4][u][4], zero both h buffers ----
    for (int i = tid; i < 96 * 64; i += 512) {
        int gi = i >> 6, k4 = i & 63;
        int g = gi >> 5, u = gi & 31;
        float4 v = *reinterpret_cast<const float4*>(
            &whh[(size_t)((g << 8) + (crank << 5) + u) * Hv + (k4 << 2)]);
        int kq = k4 >> 2, j4 = k4 & 3;
        *reinterpret_cast<float4*>(&swp[(((kq * 3 + g) << 2) + j4) * 128 + (u << 2)]) = v;
    }
    for (int i = tid; i < 4096; i += 512) shT[i] = 0.f;
    if (tid == 0) {
        uint32_t mb;
        asm("{ .reg .u64 t; cvta.to.shared.u64 t, %1; cvt.u32.u64 %0, t; }"
            : "=r"(mb) : "l"(mbar));
        asm volatile("mbarrier.init.shared.b64 [%0], %1;" :: "r"(mb), "r"(1) : "memory");
    }
    __syncthreads();
    asm volatile("barrier.cluster.arrive.aligned;" ::: "memory");
    asm volatile("barrier.cluster.wait.aligned;"   ::: "memory");

    // dot role
    int ud = tid & 31, kq = tid >> 5;
    // r-gate weights in registers (loaded once)
    float wreg[16];
#pragma unroll
    for (int j4 = 0; j4 < 4; j4++) {
        float4 wv = *reinterpret_cast<const float4*>(
            &swp[(((kq * 3 + 0) << 2) + j4) * 128 + (ud << 2)]);
        wreg[(j4 << 2) + 0] = wv.x; wreg[(j4 << 2) + 1] = wv.y;
        wreg[(j4 << 2) + 2] = wv.z; wreg[(j4 << 2) + 3] = wv.w;
    }

    // gate role
    int ugate = tid >> 3, blg = tid & 7;
    int ugx = (crank << 5) + ugate;
    int bgl = (bg << 3) + blg;
    float br = 0.f, bz = 0.f, bn2 = 0.f;
    int qm1 = -2;
    const float* xgb = nullptr;
    if (tid < 256) {
        br = bhh[ugx]; bz = bhh[256 + ugx]; bn2 = bhh[512 + ugx];
        if (gru == 0) qm1 = qlen[bgl] - 1;
        xgb = xg + (size_t)bgl * T * G3;
    }

    uint32_t shT_u32, mbar_u32, stg_u32;
    asm("{ .reg .u64 t; cvta.to.shared.u64 t, %1; cvt.u32.u64 %0, t; }"
        : "=r"(shT_u32) : "l"(shT));
    asm("{ .reg .u64 t; cvta.to.shared.u64 t, %1; cvt.u32.u64 %0, t; }"
        : "=r"(mbar_u32) : "l"(mbar));
    asm("{ .reg .u64 t; cvta.to.shared.u64 t, %1; cvt.u32.u64 %0, t; }"
        : "=r"(stg_u32) : "l"(stg));

    // bulk-copy role (tid<8): remote destination + remote barrier, per target rank
    uint32_t dstA = 0, dstB = 0, rmbar = 0;
    if (tid < 8) {
        uint32_t l0 = shT_u32 + 8192u + (uint32_t)(crank << 10);  // p=0 -> buf1
        uint32_t l1 = shT_u32 + (uint32_t)(crank << 10);          // p=1 -> buf0
        asm("mapa.shared::cluster.u32 %0, %1, %2;" : "=r"(dstA)  : "r"(l0), "r"(tid));
        asm("mapa.shared::cluster.u32 %0, %1, %2;" : "=r"(dstB)  : "r"(l1), "r"(tid));
        asm("mapa.shared::cluster.u32 %0, %1, %2;" : "=r"(rmbar) : "r"(mbar_u32), "r"(tid));
    }

    int redbase_st = ud * RED_USTR + kq;
    int redbase_ld = (tid / 12) * RED_USTR + (tid % 12) * RED_GSTR;

    for (int step = 0; step < T; step++) {
        int t = (gru == 2) ? (T - 1 - step) : step;
        int p = step & 1;

        // post expected tx for this step's incoming broadcasts (8 x 1KB)
        if (tid == 0) {
            asm volatile("mbarrier.arrive.expect_tx.shared.b64 _, [%0], %1;"
                         :: "r"(mbar_u32), "r"(8192) : "memory");
        }

        // gate-role prefetch (LDG latency hides under the dot phase)
        float ir = 0.f, iz = 0.f, in_ = 0.f, hold = 0.f;
        if (tid < 256) {
            const float* xr = xgb + (size_t)t * G3;
            ir = xr[ugx]; iz = xr[256 + ugx]; in_ = xr[512 + ugx];
            hold = shT[((p << 8) + ugx) * 8 + blg];
        }

        // ---- dot: 3 gates x 16 k x 8 batches per thread ----
        unsigned long long acc[3][4];
#pragma unroll
        for (int g = 0; g < 3; g++)
#pragma unroll
            for (int bp = 0; bp < 4; bp++) acc[g][bp] = 0ull;

        const float* hT = shT + ((p << 8) + (kq << 4)) * 8;
#pragma unroll
        for (int j4 = 0; j4 < 4; j4++) {
            ulonglong2 h01[4], h45[4];
#pragma unroll
            for (int kk = 0; kk < 4; kk++) {
                const ulonglong2* hr = reinterpret_cast<const ulonglong2*>(
                    hT + ((j4 << 2) + kk) * 8);
                h01[kk] = hr[0];
                h45[kk] = hr[1];
            }
            // g = 0 (reset gate) from registers
#pragma unroll
            for (int kk = 0; kk < 4; kk++) {
                unsigned long long wd; DUP2(wd, wreg[(j4 << 2) + kk]);
                FFMA2(acc[0][0], wd, h01[kk].x);
                FFMA2(acc[0][1], wd, h01[kk].y);
                FFMA2(acc[0][2], wd, h45[kk].x);
                FFMA2(acc[0][3], wd, h45[kk].y);
            }
            // g = 1,2 from smem
#pragma unroll
            for (int g = 1; g < 3; g++) {
                float4 wv = *reinterpret_cast<const float4*>(
                    &swp[(((kq * 3 + g) << 2) + j4) * 128 + (ud << 2)]);
                float wf[4] = {wv.x, wv.y, wv.z, wv.w};
#pragma unroll
                for (int kk = 0; kk < 4; kk++) {
                    unsigned long long wd; DUP2(wd, wf[kk]);
                    FFMA2(acc[g][0], wd, h01[kk].x);
                    FFMA2(acc[g][1], wd, h01[kk].y);
                    FFMA2(acc[g][2], wd, h45[kk].x);
                    FFMA2(acc[g][3], wd, h45[kk].y);
                }
            }
        }
#pragma unroll
        for (int g = 0; g < 3; g++)
#pragma unroll
            for (int bp = 0; bp < 4; bp++)
                redv[redbase_st + ((g << 2) + bp) * RED_GSTR] = acc[g][bp];
        __syncthreads();

        // ---- reduce over 16 kq ----
        if (tid < 384) {
            const unsigned long long* rp = redv + redbase_ld;
            unsigned long long s0 = rp[0], s1 = rp[1], s2 = rp[2], s3 = rp[3];
            ADDF2(s0, s0, rp[4]);  ADDF2(s1, s1, rp[5]);
            ADDF2(s2, s2, rp[6]);  ADDF2(s3, s3, rp[7]);
            ADDF2(s0, s0, rp[8]);  ADDF2(s1, s1, rp[9]);
            ADDF2(s2, s2, rp[10]); ADDF2(s3, s3, rp[11]);
            ADDF2(s0, s0, rp[12]); ADDF2(s1, s1, rp[13]);
            ADDF2(s2, s2, rp[14]); ADDF2(s3, s3, rp[15]);
            ADDF2(s0, s0, s1); ADDF2(s2, s2, s3);
            ADDF2(s0, s0, s2);
            rsum[tid] = s0;
        }
        __syncthreads();

        // ---- gates ----
        if (tid < 256) {
            int bp = blg >> 1, sel = blg & 1;
            float lo, hi;
            unpack2(rsum[ugate * 12 + 0 * 4 + bp], lo, hi);
            float ghr = (sel ? hi : lo) + br;
            unpack2(rsum[ugate * 12 + 1 * 4 + bp], lo, hi);
            float ghz = (sel ? hi : lo) + bz;
            unpack2(rsum[ugate * 12 + 2 * 4 + bp], lo, hi);
            float ghn = (sel ? hi : lo) + bn2;

            float r = fast_sigmoid(ir + ghr);
            float z = fast_sigmoid(iz + ghz);
            float n = fast_tanh(in_ + r * ghn);
            float hnew = (1.f - z) * n + z * hold;
            stg[(p << 8) + tid] = hnew;
            if (gru == 0) {
                if (t == qm1) d_out[(size_t)bgl * Hv + ugx] = hnew;
            } else {
                hout[((size_t)bgl * Sv + t) * Hv + ugx] = hnew;
            }
        }
        __syncthreads();

        // ---- broadcast: 8 async 1KB bulk copies (one per target CTA) ----
        if (tid < 8) {
            asm volatile("fence.proxy.async.shared::cta;" ::: "memory");
            uint32_t dst = p ? dstB : dstA;
            uint32_t src = stg_u32 + (uint32_t)(p << 10);
            asm volatile(
                "cp.async.bulk.shared::cluster.shared::cta.mbarrier::complete_tx::bytes "
                "[%0], [%1], %2, [%3];"
                :: "r"(dst), "r"(src), "r"(1024), "r"(rmbar) : "memory");
        }
        mbar_wait_cluster(mbar_u32, (uint32_t)(step & 1));
    }
}

// ---------------- combine: f_out = hf + hb, plus num_facts ----------------
__global__ void combine_kernel(const int* __restrict__ slen, float* __restrict__ d_out) {
    int idx = blockIdx.x * blockDim.x + threadIdx.x;
    const int NF4 = (Bv * Sv * Hv) / 4;
    if (idx < NF4) {
        const float4* hf4 = reinterpret_cast<const float4*>(g_hf);
        const float4* hb4 = reinterpret_cast<const float4*>(g_hb);
        float4 a = hf4[idx], c = hb4[idx];
        float4 o = make_float4(a.x + c.x, a.y + c.y, a.z + c.z, a.w + c.w);
        reinterpret_cast<float4*>(d_out + Bv * Hv)[idx] = o;
    }
    if (idx < Bv) {
        int c = 0;
        const int* sl = slen + idx * Sv;
        for (int s = 0; s < Sv; s++) c += (sl[s] > 0) ? 1 : 0;
        d_out[Bv * Hv + Bv * Sv * Hv + idx] = (float)c;
    }
}

// ---------------- launch ----------------
extern "C" void kernel_launch(void* const* d_in, const int* in_sizes, int n_in,
                              void* d_out, int out_size) {
    const int*   queries = (const int*)d_in[0];
    const int*   qlen    = (const int*)d_in[1];
    const int*   docs    = (const int*)d_in[2];
    const int*   slen    = (const int*)d_in[3];
    const float* emb     = (const float*)d_in[4];
    const float* q_wih   = (const float*)d_in[5];
    const float* q_whh   = (const float*)d_in[6];
    const float* q_bih   = (const float*)d_in[7];
    const float* q_bhh   = (const float*)d_in[8];
    const float* f_wih   = (const float*)d_in[9];
    const float* f_whh   = (const float*)d_in[10];
    const float* f_bih   = (const float*)d_in[11];
    const float* f_bhh   = (const float*)d_in[12];
    const float* b_wih   = (const float*)d_in[13];
    const float* b_whh   = (const float*)d_in[14];
    const float* b_bih   = (const float*)d_in[15];
    const float* b_bhh   = (const float*)d_in[16];
    float* out = (float*)d_out;

    // floats: swp 24576 + shT 4096 + red 13120 + rsum 768 + stg 512, + mbar 16B
    const int GRU_SMEM = (24576 + 4096 + 32 * RED_USTR * 2 + 384 * 2 + 512) * 4 + 32;
    cudaFuncSetAttribute(gru_cluster, cudaFuncAttributeMaxDynamicSharedMemorySize, GRU_SMEM);

    facts_kernel<<<Bv * Sv, 320>>>(docs, slen, emb);

    dim3 gg(6, 20);
    xg_gemm<<<gg, 512>>>(queries, emb, q_wih, f_wih, b_wih, q_bih, f_bih, b_bih);

    gru_cluster<<<96, 512, GRU_SMEM>>>(qlen, q_whh, f_whh, b_whh,
                                       q_bhh, f_bhh, b_bhh, out);

    combine_kernel<<<(Bv * Sv * Hv / 4 + 255) / 256, 256>>>(slen, out);
}

// round 9
// speedup vs baseline: 1.3298x; 1.0006x over previous
#include <cuda_runtime.h>
#include <math.h>
#include <stdint.h>

#define Bv   32
#define QL   32
#define DOCL 2048
#define Sv   64
#define Ev   300
#define Hv   256
#define G3   768    // 3*H
#define KP   304    // padded K for GEMM
#define CLS  8      // cluster size

// ---------------- scratch ----------------
__device__ float g_facts[Bv*Sv*Ev];
__device__ float g_xg_q[Bv*QL*G3];
__device__ float g_xg_f[Bv*Sv*G3];
__device__ float g_xg_b[Bv*Sv*G3];
__device__ float g_hf[Bv*Sv*Hv];
__device__ float g_hb[Bv*Sv*Hv];

// packed 2xfp32 ops
#define FFMA2(acc, a, b) asm("fma.rn.f32x2 %0, %1, %2, %0;" : "+l"(acc) : "l"(a), "l"(b))
#define ADDF2(o, a, b)   asm("add.rn.f32x2 %0, %1, %2;" : "=l"(o) : "l"(a), "l"(b))
#define DUP2(d, s)       asm("mov.b64 %0, {%1, %1};" : "=l"(d) : "f"(s))

__device__ __forceinline__ void unpack2(unsigned long long v, float& lo, float& hi) {
    asm("mov.b64 {%0,%1}, %2;" : "=f"(lo), "=f"(hi) : "l"(v));
}
__device__ __forceinline__ float fast_sigmoid(float x) {
    return 1.f / (1.f + __expf(-x));
}
__device__ __forceinline__ float fast_tanh(float x) {
    return 2.f / (1.f + __expf(-2.f * x)) - 1.f;
}
__device__ __forceinline__ void mbar_wait_cluster(uint32_t mbar, uint32_t parity) {
    asm volatile(
        "{\n\t"
        ".reg .pred P;\n\t"
        "MWL_%=:\n\t"
        "mbarrier.try_wait.parity.acquire.cluster.shared::cta.b64 P, [%0], %1, 0x989680;\n\t"
        "@!P bra MWL_%=;\n\t"
        "}" :: "r"(mbar), "r"(parity) : "memory");
}

// ---------------- facts: ragged per-sentence mean pooling ----------------
__global__ void facts_kernel(const int* __restrict__ docs,
                             const int* __restrict__ slen,
                             const float* __restrict__ emb) {
    __shared__ int toks[DOCL];
    int bs = blockIdx.x;
    int b = bs >> 6, s = bs & 63;
    const int* sl = slen + b * Sv;
    int start = 0;
    for (int i = 0; i < s; i++) start += sl[i];
    int len = sl[s];
    if (len > DOCL - start) len = DOCL - start;
    const int* dp = docs + b * DOCL + start;
    for (int i = threadIdx.x; i < len; i += blockDim.x) toks[i] = dp[i];
    __syncthreads();
    int e = threadIdx.x;
    if (e < Ev) {
        float acc = 0.f;
        for (int i = 0; i < len; i++)
            acc += emb[(size_t)toks[i] * Ev + e];
        float d = (len > 0) ? (float)len : 1.0f;
        g_facts[(size_t)bs * Ev + e] = acc / d;
    }
}

// ---------------- merged xg GEMM: 5120 x 768 x 304 (unchanged) ----------------
__global__ __launch_bounds__(512, 1) void xg_gemm(
        const int* __restrict__ queries, const float* __restrict__ emb,
        const float* __restrict__ qwih, const float* __restrict__ fwih,
        const float* __restrict__ bwih,
        const float* __restrict__ qbih, const float* __restrict__ fbih,
        const float* __restrict__ bbih) {
    __shared__ float As[16][264];
    __shared__ float Bs[16][132];

    int m0 = blockIdx.y * 256, n0 = blockIdx.x * 128;
    int which = (m0 < 1024) ? 0 : ((m0 < 3072) ? 1 : 2);
    int mbase = (which == 0) ? 0 : (which == 1) ? 1024 : 3072;
    const float* wih = (which == 0) ? qwih : (which == 1) ? fwih : bwih;
    const float* bih = (which == 0) ? qbih : (which == 1) ? fbih : bbih;
    float* outb = ((which == 0) ? g_xg_q : (which == 1) ? g_xg_f : g_xg_b)
                  + (size_t)(m0 - mbase) * G3;

    int tid = threadIdx.x, tx = tid & 15, ty = tid >> 4;

    const float* asrc[2];
    int ac[2];
#pragma unroll
    for (int i = 0; i < 2; i++) {
        int idx = tid + i * 512;
        int r = idx >> 2;
        ac[i] = idx & 3;
        int m = m0 + r;
        asrc[i] = (which == 0) ? (emb + (size_t)queries[m] * Ev)
                               : (g_facts + (size_t)(m - mbase) * Ev);
    }
    int ar0 = (tid) >> 2, ar1 = (tid + 512) >> 2;
    int bn = tid >> 2, bkq = tid & 3;
    const float* brow = wih + (size_t)(n0 + bn) * Ev;

    unsigned long long acc[8][4];
#pragma unroll
    for (int i = 0; i < 8; i++)
#pragma unroll
        for (int j = 0; j < 4; j++) acc[i][j] = 0ull;

    for (int k0 = 0; k0 < KP; k0 += 16) {
#pragma unroll
        for (int i = 0; i < 2; i++) {
            int k = k0 + ac[i] * 4;
            float4 av = (k < Ev) ? *reinterpret_cast<const float4*>(asrc[i] + k)
                                 : make_float4(0.f, 0.f, 0.f, 0.f);
            int r = (i == 0) ? ar0 : ar1;
            As[ac[i]*4+0][r] = av.x; As[ac[i]*4+1][r] = av.y;
            As[ac[i]*4+2][r] = av.z; As[ac[i]*4+3][r] = av.w;
        }
        {
            int k = k0 + bkq * 4;
            float4 bv = (k < Ev) ? *reinterpret_cast<const float4*>(brow + k)
                                 : make_float4(0.f, 0.f, 0.f, 0.f);
            Bs[bkq*4+0][bn] = bv.x; Bs[bkq*4+1][bn] = bv.y;
            Bs[bkq*4+2][bn] = bv.z; Bs[bkq*4+3][bn] = bv.w;
        }
        __syncthreads();
#pragma unroll
        for (int k = 0; k < 16; k++) {
            float4 a0 = *reinterpret_cast<const float4*>(&As[k][ty * 8]);
            float4 a1 = *reinterpret_cast<const float4*>(&As[k][ty * 8 + 4]);
            ulonglong2 b01 = *reinterpret_cast<const ulonglong2*>(&Bs[k][tx * 8]);
            ulonglong2 b23 = *reinterpret_cast<const ulonglong2*>(&Bs[k][tx * 8 + 4]);
            float af[8] = {a0.x, a0.y, a0.z, a0.w, a1.x, a1.y, a1.z, a1.w};
#pragma unroll
            for (int i = 0; i < 8; i++) {
                unsigned long long ad; DUP2(ad, af[i]);
                FFMA2(acc[i][0], ad, b01.x);
                FFMA2(acc[i][1], ad, b01.y);
                FFMA2(acc[i][2], ad, b23.x);
                FFMA2(acc[i][3], ad, b23.y);
            }
        }
        __syncthreads();
    }
#pragma unroll
    for (int i = 0; i < 8; i++) {
        float* orow = outb + (size_t)(ty * 8 + i) * G3 + n0 + tx * 8;
#pragma unroll
        for (int jp = 0; jp < 4; jp++) {
            float lo, hi; unpack2(acc[i][jp], lo, hi);
            orow[2*jp]   = lo + bih[n0 + tx*8 + 2*jp];
            orow[2*jp+1] = hi + bih[n0 + tx*8 + 2*jp + 1];
        }
    }
}

// ---------------- GRU: weight-amortized, mbarrier-tx synced, merged reduce+gates ----
// 12 clusters x 8 CTAs x 512 threads.
// Dot role:  ud = tid&31 (unit), kq = tid>>5 (k-chunk of 16); 8 batches in f32x2 pairs.
//            r & z gate weights in registers; n gate from smem.
// Gate role: tid<128: u = tid>>2, bp = tid&3 (batch pair); sums own kq partials,
//            computes gates for 2 batches, writes stg + gmem.
#define RED_USTR 205
#define RED_GSTR 17
extern "C" __global__ void __cluster_dims__(CLS, 1, 1) __launch_bounds__(512, 1)
gru_cluster(const int* __restrict__ qlen,
            const float* __restrict__ qwhh, const float* __restrict__ fwhh,
            const float* __restrict__ bwhh,
            const float* __restrict__ qbhh, const float* __restrict__ fbhh,
            const float* __restrict__ bbhh,
            float* __restrict__ d_out) {
    extern __shared__ float sm[];
    float* swp = sm;                                         // 24576 floats
    float* shT = sm + 24576;                                 // 4096 floats [2][256][8]
    unsigned long long* redv = (unsigned long long*)(sm + 24576 + 4096);
    float* stg = (float*)(redv + 32 * RED_USTR);             // [2][256]
    unsigned long long* mbar = (unsigned long long*)(stg + 512);

    int cid = blockIdx.x / CLS;
    int crank = blockIdx.x - cid * CLS;
    int gru = cid >> 2, bg = cid & 3;
    int tid = threadIdx.x;

    const float* whh = (gru == 0) ? qwhh : (gru == 1) ? fwhh : bwhh;
    const float* bhh = (gru == 0) ? qbhh : (gru == 1) ? fbhh : bbhh;
    const float* xg  = (gru == 0) ? g_xg_q : (gru == 1) ? g_xg_f : g_xg_b;
    float* hout = (gru == 1) ? g_hf : g_hb;
    int T = (gru == 0) ? QL : Sv;

    // ---- init: repack weights [kq][g][j4][u][4], zero both h buffers ----
    for (int i = tid; i < 96 * 64; i += 512) {
        int gi = i >> 6, k4 = i & 63;
        int g = gi >> 5, u = gi & 31;
        float4 v = *reinterpret_cast<const float4*>(
            &whh[(size_t)((g << 8) + (crank << 5) + u) * Hv + (k4 << 2)]);
        int kq = k4 >> 2, j4 = k4 & 3;
        *reinterpret_cast<float4*>(&swp[(((kq * 3 + g) << 2) + j4) * 128 + (u << 2)]) = v;
    }
    for (int i = tid; i < 4096; i += 512) shT[i] = 0.f;
    if (tid == 0) {
        uint32_t mb;
        asm("{ .reg .u64 t; cvta.to.shared.u64 t, %1; cvt.u32.u64 %0, t; }"
            : "=r"(mb) : "l"(mbar));
        asm volatile("mbarrier.init.shared.b64 [%0], %1;" :: "r"(mb), "r"(1) : "memory");
    }
    __syncthreads();
    asm volatile("barrier.cluster.arrive.aligned;" ::: "memory");
    asm volatile("barrier.cluster.wait.aligned;"   ::: "memory");

    // ---- dot role: r and z gate weights in registers ----
    int ud = tid & 31, kq = tid >> 5;
    float wrreg[16], wzreg[16];
#pragma unroll
    for (int j4 = 0; j4 < 4; j4++) {
        float4 wv = *reinterpret_cast<const float4*>(
            &swp[(((kq * 3 + 0) << 2) + j4) * 128 + (ud << 2)]);
        wrreg[(j4 << 2) + 0] = wv.x; wrreg[(j4 << 2) + 1] = wv.y;
        wrreg[(j4 << 2) + 2] = wv.z; wrreg[(j4 << 2) + 3] = wv.w;
        float4 zv = *reinterpret_cast<const float4*>(
            &swp[(((kq * 3 + 1) << 2) + j4) * 128 + (ud << 2)]);
        wzreg[(j4 << 2) + 0] = zv.x; wzreg[(j4 << 2) + 1] = zv.y;
        wzreg[(j4 << 2) + 2] = zv.z; wzreg[(j4 << 2) + 3] = zv.w;
    }

    // ---- gate role: tid<128, u = tid>>2, bp = tid&3 (2 batches) ----
    int ug = tid >> 2, bp = tid & 3;
    int ugx = (crank << 5) + ug;
    int b0 = (bg << 3) + (bp << 1), b1 = b0 + 1;
    float br = 0.f, bz = 0.f, bn2 = 0.f;
    int qm10 = -2, qm11 = -2;
    const float* xgb0 = nullptr;
    const float* xgb1 = nullptr;
    if (tid < 128) {
        br = bhh[ugx]; bz = bhh[256 + ugx]; bn2 = bhh[512 + ugx];
        if (gru == 0) { qm10 = qlen[b0] - 1; qm11 = qlen[b1] - 1; }
        xgb0 = xg + (size_t)b0 * T * G3;
        xgb1 = xg + (size_t)b1 * T * G3;
    }

    uint32_t shT_u32, mbar_u32, stg_u32;
    asm("{ .reg .u64 t; cvta.to.shared.u64 t, %1; cvt.u32.u64 %0, t; }"
        : "=r"(shT_u32) : "l"(shT));
    asm("{ .reg .u64 t; cvta.to.shared.u64 t, %1; cvt.u32.u64 %0, t; }"
        : "=r"(mbar_u32) : "l"(mbar));
    asm("{ .reg .u64 t; cvta.to.shared.u64 t, %1; cvt.u32.u64 %0, t; }"
        : "=r"(stg_u32) : "l"(stg));

    // bulk-copy role (tid<8)
    uint32_t dstA = 0, dstB = 0, rmbar = 0;
    if (tid < 8) {
        uint32_t l0 = shT_u32 + 8192u + (uint32_t)(crank << 10);  // p=0 -> buf1
        uint32_t l1 = shT_u32 + (uint32_t)(crank << 10);          // p=1 -> buf0
        asm("mapa.shared::cluster.u32 %0, %1, %2;" : "=r"(dstA)  : "r"(l0), "r"(tid));
        asm("mapa.shared::cluster.u32 %0, %1, %2;" : "=r"(dstB)  : "r"(l1), "r"(tid));
        asm("mapa.shared::cluster.u32 %0, %1, %2;" : "=r"(rmbar) : "r"(mbar_u32), "r"(tid));
    }

    int redbase_st = ud * RED_USTR + kq;

    for (int step = 0; step < T; step++) {
        int t = (gru == 2) ? (T - 1 - step) : step;
        int p = step & 1;

        if (tid == 0) {
            asm volatile("mbarrier.arrive.expect_tx.shared.b64 _, [%0], %1;"
                         :: "r"(mbar_u32), "r"(8192) : "memory");
        }

        // gate-role x prefetch (LDG latency hides under the dot phase)
        float ir0 = 0.f, iz0 = 0.f, in0 = 0.f, hold0 = 0.f;
        float ir1 = 0.f, iz1 = 0.f, in1 = 0.f, hold1 = 0.f;
        if (tid < 128) {
            const float* xr0 = xgb0 + (size_t)t * G3;
            const float* xr1 = xgb1 + (size_t)t * G3;
            ir0 = xr0[ugx]; iz0 = xr0[256 + ugx]; in0 = xr0[512 + ugx];
            ir1 = xr1[ugx]; iz1 = xr1[256 + ugx]; in1 = xr1[512 + ugx];
            hold0 = shT[((p << 8) + ugx) * 8 + (bp << 1)];
            hold1 = shT[((p << 8) + ugx) * 8 + (bp << 1) + 1];
        }

        // ---- dot: 3 gates x 16 k x 8 batches per thread ----
        unsigned long long acc[3][4];
#pragma unroll
        for (int g = 0; g < 3; g++)
#pragma unroll
            for (int b = 0; b < 4; b++) acc[g][b] = 0ull;

        const float* hT = shT + ((p << 8) + (kq << 4)) * 8;
#pragma unroll
        for (int j4 = 0; j4 < 4; j4++) {
            ulonglong2 h01[4], h45[4];
#pragma unroll
            for (int kk = 0; kk < 4; kk++) {
                const ulonglong2* hr = reinterpret_cast<const ulonglong2*>(
                    hT + ((j4 << 2) + kk) * 8);
                h01[kk] = hr[0];
                h45[kk] = hr[1];
            }
            // r gate (registers)
#pragma unroll
            for (int kk = 0; kk < 4; kk++) {
                unsigned long long wd; DUP2(wd, wrreg[(j4 << 2) + kk]);
                FFMA2(acc[0][0], wd, h01[kk].x);
                FFMA2(acc[0][1], wd, h01[kk].y);
                FFMA2(acc[0][2], wd, h45[kk].x);
                FFMA2(acc[0][3], wd, h45[kk].y);
            }
            // z gate (registers)
#pragma unroll
            for (int kk = 0; kk < 4; kk++) {
                unsigned long long wd; DUP2(wd, wzreg[(j4 << 2) + kk]);
                FFMA2(acc[1][0], wd, h01[kk].x);
                FFMA2(acc[1][1], wd, h01[kk].y);
                FFMA2(acc[1][2], wd, h45[kk].x);
                FFMA2(acc[1][3], wd, h45[kk].y);
            }
            // n gate (smem)
            {
                float4 wv = *reinterpret_cast<const float4*>(
                    &swp[(((kq * 3 + 2) << 2) + j4) * 128 + (ud << 2)]);
                float wf[4] = {wv.x, wv.y, wv.z, wv.w};
#pragma unroll
                for (int kk = 0; kk < 4; kk++) {
                    unsigned long long wd; DUP2(wd, wf[kk]);
                    FFMA2(acc[2][0], wd, h01[kk].x);
                    FFMA2(acc[2][1], wd, h01[kk].y);
                    FFMA2(acc[2][2], wd, h45[kk].x);
                    FFMA2(acc[2][3], wd, h45[kk].y);
                }
            }
        }
#pragma unroll
        for (int g = 0; g < 3; g++)
#pragma unroll
            for (int b = 0; b < 4; b++)
                redv[redbase_st + ((g << 2) + b) * RED_GSTR] = acc[g][b];
        __syncthreads();

        // ---- merged reduce + gates: 128 threads, 2 batches each ----
        if (tid < 128) {
            unsigned long long s[3];
#pragma unroll
            for (int g = 0; g < 3; g++) {
                const unsigned long long* rp =
                    redv + ug * RED_USTR + ((g << 2) + bp) * RED_GSTR;
                unsigned long long s0 = rp[0], s1 = rp[1], s2 = rp[2], s3 = rp[3];
                ADDF2(s0, s0, rp[4]);  ADDF2(s1, s1, rp[5]);
                ADDF2(s2, s2, rp[6]);  ADDF2(s3, s3, rp[7]);
                ADDF2(s0, s0, rp[8]);  ADDF2(s1, s1, rp[9]);
                ADDF2(s2, s2, rp[10]); ADDF2(s3, s3, rp[11]);
                ADDF2(s0, s0, rp[12]); ADDF2(s1, s1, rp[13]);
                ADDF2(s2, s2, rp[14]); ADDF2(s3, s3, rp[15]);
                ADDF2(s0, s0, s1); ADDF2(s2, s2, s3);
                ADDF2(s0, s0, s2);
                s[g] = s0;
            }
            float ghr0, ghr1, ghz0, ghz1, ghn0, ghn1;
            unpack2(s[0], ghr0, ghr1);
            unpack2(s[1], ghz0, ghz1);
            unpack2(s[2], ghn0, ghn1);

            float r0 = fast_sigmoid(ir0 + ghr0 + br);
            float z0 = fast_sigmoid(iz0 + ghz0 + bz);
            float n0 = fast_tanh(in0 + r0 * (ghn0 + bn2));
            float hnew0 = (1.f - z0) * n0 + z0 * hold0;
            float r1 = fast_sigmoid(ir1 + ghr1 + br);
            float z1 = fast_sigmoid(iz1 + ghz1 + bz);
            float n1 = fast_tanh(in1 + r1 * (ghn1 + bn2));
            float hnew1 = (1.f - z1) * n1 + z1 * hold1;

            stg[(p << 8) + (ug << 3) + (bp << 1)]     = hnew0;
            stg[(p << 8) + (ug << 3) + (bp << 1) + 1] = hnew1;
            if (gru == 0) {
                if (t == qm10) d_out[(size_t)b0 * Hv + ugx] = hnew0;
                if (t == qm11) d_out[(size_t)b1 * Hv + ugx] = hnew1;
            } else {
                hout[((size_t)b0 * Sv + t) * Hv + ugx] = hnew0;
                hout[((size_t)b1 * Sv + t) * Hv + ugx] = hnew1;
            }
        }
        __syncthreads();

        // ---- broadcast: 8 async 1KB bulk copies (one per target CTA) ----
        if (tid < 8) {
            asm volatile("fence.proxy.async.shared::cta;" ::: "memory");
            uint32_t dst = p ? dstB : dstA;
            uint32_t src = stg_u32 + (uint32_t)(p << 10);
            asm volatile(
                "cp.async.bulk.shared::cluster.shared::cta.mbarrier::complete_tx::bytes "
                "[%0], [%1], %2, [%3];"
                :: "r"(dst), "r"(src), "r"(1024), "r"(rmbar) : "memory");
        }
        mbar_wait_cluster(mbar_u32, (uint32_t)(step & 1));
    }
}

// ---------------- combine: f_out = hf + hb, plus num_facts ----------------
__global__ void combine_kernel(const int* __restrict__ slen, float* __restrict__ d_out) {
    int idx = blockIdx.x * blockDim.x + threadIdx.x;
    const int NF4 = (Bv * Sv * Hv) / 4;
    if (idx < NF4) {
        const float4* hf4 = reinterpret_cast<const float4*>(g_hf);
        const float4* hb4 = reinterpret_cast<const float4*>(g_hb);
        float4 a = hf4[idx], c = hb4[idx];
        float4 o = make_float4(a.x + c.x, a.y + c.y, a.z + c.z, a.w + c.w);
        reinterpret_cast<float4*>(d_out + Bv * Hv)[idx] = o;
    }
    if (idx < Bv) {
        int c = 0;
        const int* sl = slen + idx * Sv;
        for (int s = 0; s < Sv; s++) c += (sl[s] > 0) ? 1 : 0;
        d_out[Bv * Hv + Bv * Sv * Hv + idx] = (float)c;
    }
}

// ---------------- launch ----------------
extern "C" void kernel_launch(void* const* d_in, const int* in_sizes, int n_in,
                              void* d_out, int out_size) {
    const int*   queries = (const int*)d_in[0];
    const int*   qlen    = (const int*)d_in[1];
    const int*   docs    = (const int*)d_in[2];
    const int*   slen    = (const int*)d_in[3];
    const float* emb     = (const float*)d_in[4];
    const float* q_wih   = (const float*)d_in[5];
    const float* q_whh   = (const float*)d_in[6];
    const float* q_bih   = (const float*)d_in[7];
    const float* q_bhh   = (const float*)d_in[8];
    const float* f_wih   = (const float*)d_in[9];
    const float* f_whh   = (const float*)d_in[10];
    const float* f_bih   = (const float*)d_in[11];
    const float* f_bhh   = (const float*)d_in[12];
    const float* b_wih   = (const float*)d_in[13];
    const float* b_whh   = (const float*)d_in[14];
    const float* b_bih   = (const float*)d_in[15];
    const float* b_bhh   = (const float*)d_in[16];
    float* out = (float*)d_out;

    // floats: swp 24576 + shT 4096 + redv 13120 + stg 512, + mbar pad
    const int GRU_SMEM = (24576 + 4096 + 32 * RED_USTR * 2 + 512) * 4 + 32;
    cudaFuncSetAttribute(gru_cluster, cudaFuncAttributeMaxDynamicSharedMemorySize, GRU_SMEM);

    facts_kernel<<<Bv * Sv, 320>>>(docs, slen, emb);

    dim3 gg(6, 20);
    xg_gemm<<<gg, 512>>>(queries, emb, q_wih, f_wih, b_wih, q_bih, f_bih, b_bih);

    gru_cluster<<<96, 512, GRU_SMEM>>>(qlen, q_whh, f_whh, b_whh,
                                       q_bhh, f_bhh, b_bhh, out);

    combine_kernel<<<(Bv * Sv * Hv / 4 + 255) / 256, 256>>>(slen, out);
}

// round 11
// speedup vs baseline: 1.3471x; 1.0130x over previous
#include <cuda_runtime.h>
#include <math.h>
#include <stdint.h>

#define Bv   32
#define QL   32
#define DOCL 2048
#define Sv   64
#define Ev   300
#define Hv   256
#define G3   768    // 3*H
#define KP   304    // padded K for GEMM
#define CLS  8      // cluster size

// ---------------- scratch ----------------
__device__ float g_facts[Bv*Sv*Ev];
__device__ float g_xg_q[Bv*QL*G3];
__device__ float g_xg_f[Bv*Sv*G3];
__device__ float g_xg_b[Bv*Sv*G3];
__device__ float g_hf[Bv*Sv*Hv];
__device__ float g_hb[Bv*Sv*Hv];

// packed 2xfp32 ops
#define FFMA2(acc, a, b) asm("fma.rn.f32x2 %0, %1, %2, %0;" : "+l"(acc) : "l"(a), "l"(b))
#define ADDF2(o, a, b)   asm("add.rn.f32x2 %0, %1, %2;" : "=l"(o) : "l"(a), "l"(b))
#define DUP2(d, s)       asm("mov.b64 %0, {%1, %1};" : "=l"(d) : "f"(s))

__device__ __forceinline__ void unpack2(unsigned long long v, float& lo, float& hi) {
    asm("mov.b64 {%0,%1}, %2;" : "=f"(lo), "=f"(hi) : "l"(v));
}
__device__ __forceinline__ float fast_sigmoid(float x) {
    return 1.f / (1.f + __expf(-x));
}
__device__ __forceinline__ float fast_tanh(float x) {
    return 2.f / (1.f + __expf(-2.f * x)) - 1.f;
}
__device__ __forceinline__ void mbar_wait_cluster(uint32_t mbar, uint32_t parity) {
    asm volatile(
        "{\n\t"
        ".reg .pred P;\n\t"
        "MWL_%=:\n\t"
        "mbarrier.try_wait.parity.acquire.cluster.shared::cta.b64 P, [%0], %1, 0x989680;\n\t"
        "@!P bra MWL_%=;\n\t"
        "}" :: "r"(mbar), "r"(parity) : "memory");
}

// ---------------- facts: ragged per-sentence mean pooling ----------------
__global__ void facts_kernel(const int* __restrict__ docs,
                             const int* __restrict__ slen,
                             const float* __restrict__ emb) {
    __shared__ int toks[DOCL];
    int bs = blockIdx.x;
    int b = bs >> 6, s = bs & 63;
    const int* sl = slen + b * Sv;
    int start = 0;
    for (int i = 0; i < s; i++) start += sl[i];
    int len = sl[s];
    if (len > DOCL - start) len = DOCL - start;
    const int* dp = docs + b * DOCL + start;
    for (int i = threadIdx.x; i < len; i += blockDim.x) toks[i] = dp[i];
    __syncthreads();
    int e = threadIdx.x;
    if (e < Ev) {
        float a0 = 0.f, a1 = 0.f, a2 = 0.f, a3 = 0.f;
        int i = 0;
        for (; i + 4 <= len; i += 4) {
            a0 += emb[(size_t)toks[i]     * Ev + e];
            a1 += emb[(size_t)toks[i + 1] * Ev + e];
            a2 += emb[(size_t)toks[i + 2] * Ev + e];
            a3 += emb[(size_t)toks[i + 3] * Ev + e];
        }
        for (; i < len; i++) a0 += emb[(size_t)toks[i] * Ev + e];
        float acc = (a0 + a1) + (a2 + a3);
        float d = (len > 0) ? (float)len : 1.0f;
        g_facts[(size_t)bs * Ev + e] = acc / d;
    }
}

// ---------------- merged xg GEMM: 5120 x 768 x 304 (unchanged) ----------------
__global__ __launch_bounds__(512, 1) void xg_gemm(
        const int* __restrict__ queries, const float* __restrict__ emb,
        const float* __restrict__ qwih, const float* __restrict__ fwih,
        const float* __restrict__ bwih,
        const float* __restrict__ qbih, const float* __restrict__ fbih,
        const float* __restrict__ bbih) {
    __shared__ float As[16][264];
    __shared__ float Bs[16][132];

    int m0 = blockIdx.y * 256, n0 = blockIdx.x * 128;
    int which = (m0 < 1024) ? 0 : ((m0 < 3072) ? 1 : 2);
    int mbase = (which == 0) ? 0 : (which == 1) ? 1024 : 3072;
    const float* wih = (which == 0) ? qwih : (which == 1) ? fwih : bwih;
    const float* bih = (which == 0) ? qbih : (which == 1) ? fbih : bbih;
    float* outb = ((which == 0) ? g_xg_q : (which == 1) ? g_xg_f : g_xg_b)
                  + (size_t)(m0 - mbase) * G3;

    int tid = threadIdx.x, tx = tid & 15, ty = tid >> 4;

    const float* asrc[2];
    int ac[2];
#pragma unroll
    for (int i = 0; i < 2; i++) {
        int idx = tid + i * 512;
        int r = idx >> 2;
        ac[i] = idx & 3;
        int m = m0 + r;
        asrc[i] = (which == 0) ? (emb + (size_t)queries[m] * Ev)
                               : (g_facts + (size_t)(m - mbase) * Ev);
    }
    int ar0 = (tid) >> 2, ar1 = (tid + 512) >> 2;
    int bn = tid >> 2, bkq = tid & 3;
    const float* brow = wih + (size_t)(n0 + bn) * Ev;

    unsigned long long acc[8][4];
#pragma unroll
    for (int i = 0; i < 8; i++)
#pragma unroll
        for (int j = 0; j < 4; j++) acc[i][j] = 0ull;

    for (int k0 = 0; k0 < KP; k0 += 16) {
#pragma unroll
        for (int i = 0; i < 2; i++) {
            int k = k0 + ac[i] * 4;
            float4 av = (k < Ev) ? *reinterpret_cast<const float4*>(asrc[i] + k)
                                 : make_float4(0.f, 0.f, 0.f, 0.f);
            int r = (i == 0) ? ar0 : ar1;
            As[ac[i]*4+0][r] = av.x; As[ac[i]*4+1][r] = av.y;
            As[ac[i]*4+2][r] = av.z; As[ac[i]*4+3][r] = av.w;
        }
        {
            int k = k0 + bkq * 4;
            float4 bv = (k < Ev) ? *reinterpret_cast<const float4*>(brow + k)
                                 : make_float4(0.f, 0.f, 0.f, 0.f);
            Bs[bkq*4+0][bn] = bv.x; Bs[bkq*4+1][bn] = bv.y;
            Bs[bkq*4+2][bn] = bv.z; Bs[bkq*4+3][bn] = bv.w;
        }
        __syncthreads();
#pragma unroll
        for (int k = 0; k < 16; k++) {
            float4 a0 = *reinterpret_cast<const float4*>(&As[k][ty * 8]);
            float4 a1 = *reinterpret_cast<const float4*>(&As[k][ty * 8 + 4]);
            ulonglong2 b01 = *reinterpret_cast<const ulonglong2*>(&Bs[k][tx * 8]);
            ulonglong2 b23 = *reinterpret_cast<const ulonglong2*>(&Bs[k][tx * 8 + 4]);
            float af[8] = {a0.x, a0.y, a0.z, a0.w, a1.x, a1.y, a1.z, a1.w};
#pragma unroll
            for (int i = 0; i < 8; i++) {
                unsigned long long ad; DUP2(ad, af[i]);
                FFMA2(acc[i][0], ad, b01.x);
                FFMA2(acc[i][1], ad, b01.y);
                FFMA2(acc[i][2], ad, b23.x);
                FFMA2(acc[i][3], ad, b23.y);
            }
        }
        __syncthreads();
    }
#pragma unroll
    for (int i = 0; i < 8; i++) {
        float* orow = outb + (size_t)(ty * 8 + i) * G3 + n0 + tx * 8;
#pragma unroll
        for (int jp = 0; jp < 4; jp++) {
            float lo, hi; unpack2(acc[i][jp], lo, hi);
            orow[2*jp]   = lo + bih[n0 + tx*8 + 2*jp];
            orow[2*jp+1] = hi + bih[n0 + tx*8 + 2*jp + 1];
        }
    }
}

// ---------------- GRU: per-slice mbarriers, wait-then-arm protocol ----------------
// 12 clusters x 8 CTAs x 512 threads.
// Dot role:  ud = tid&31, kq = tid>>5 (16 k each); warp kq needs h only from rank kq>>1.
// Gate role: tid<128: u = tid>>2, bp = tid&3 (2 batches).
#define RED_USTR 205
#define RED_GSTR 17
extern "C" __global__ void __cluster_dims__(CLS, 1, 1) __launch_bounds__(512, 1)
gru_cluster(const int* __restrict__ qlen,
            const float* __restrict__ qwhh, const float* __restrict__ fwhh,
            const float* __restrict__ bwhh,
            const float* __restrict__ qbhh, const float* __restrict__ fbhh,
            const float* __restrict__ bbhh,
            float* __restrict__ d_out) {
    extern __shared__ float sm[];
    float* swp = sm;                                         // 24576 floats
    float* shT = sm + 24576;                                 // 4096 floats [2][256][8]
    unsigned long long* redv = (unsigned long long*)(sm + 24576 + 4096);
    float* stg = (float*)(redv + 32 * RED_USTR);             // [4][256] 4-deep
    unsigned long long* mbar = (unsigned long long*)(stg + 1024);  // [8]

    int cid = blockIdx.x / CLS;
    int crank = blockIdx.x - cid * CLS;
    int gru = cid >> 2, bg = cid & 3;
    int tid = threadIdx.x;

    const float* whh = (gru == 0) ? qwhh : (gru == 1) ? fwhh : bwhh;
    const float* bhh = (gru == 0) ? qbhh : (gru == 1) ? fbhh : bbhh;
    const float* xg  = (gru == 0) ? g_xg_q : (gru == 1) ? g_xg_f : g_xg_b;
    float* hout = (gru == 1) ? g_hf : g_hb;
    int T = (gru == 0) ? QL : Sv;

    uint32_t shT_u32, mbar_u32, stg_u32;
    asm("{ .reg .u64 t; cvta.to.shared.u64 t, %1; cvt.u32.u64 %0, t; }"
        : "=r"(shT_u32) : "l"(shT));
    asm("{ .reg .u64 t; cvta.to.shared.u64 t, %1; cvt.u32.u64 %0, t; }"
        : "=r"(mbar_u32) : "l"(mbar));
    asm("{ .reg .u64 t; cvta.to.shared.u64 t, %1; cvt.u32.u64 %0, t; }"
        : "=r"(stg_u32) : "l"(stg));

    // ---- init: repack weights; zero h + stg; init 8 mbarriers; arm phase 0 ----
    for (int i = tid; i < 96 * 64; i += 512) {
        int gi = i >> 6, k4 = i & 63;
        int g = gi >> 5, u = gi & 31;
        float4 v = *reinterpret_cast<const float4*>(
            &whh[(size_t)((g << 8) + (crank << 5) + u) * Hv + (k4 << 2)]);
        int kq = k4 >> 2, j4 = k4 & 3;
        *reinterpret_cast<float4*>(&swp[(((kq * 3 + g) << 2) + j4) * 128 + (u << 2)]) = v;
    }
    for (int i = tid; i < 4096; i += 512) shT[i] = 0.f;
    for (int i = tid; i < 1024; i += 512) stg[i] = 0.f;
    if (tid < 8) {
        asm volatile("mbarrier.init.shared.b64 [%0], %1;"
                     :: "r"(mbar_u32 + tid * 8), "r"(1) : "memory");
        // arm phase 0 before any peer can send (cluster barrier below orders this)
        asm volatile("mbarrier.arrive.expect_tx.shared.b64 _, [%0], %1;"
                     :: "r"(mbar_u32 + tid * 8), "r"(1024) : "memory");
    }
    __syncthreads();
    asm volatile("barrier.cluster.arrive.aligned;" ::: "memory");
    asm volatile("barrier.cluster.wait.aligned;"   ::: "memory");

    // ---- dot role: r and z gate weights in registers ----
    int ud = tid & 31, kq = tid >> 5;
    float wrreg[16], wzreg[16];
#pragma unroll
    for (int j4 = 0; j4 < 4; j4++) {
        float4 wv = *reinterpret_cast<const float4*>(
            &swp[(((kq * 3 + 0) << 2) + j4) * 128 + (ud << 2)]);
        wrreg[(j4 << 2) + 0] = wv.x; wrreg[(j4 << 2) + 1] = wv.y;
        wrreg[(j4 << 2) + 2] = wv.z; wrreg[(j4 << 2) + 3] = wv.w;
        float4 zv = *reinterpret_cast<const float4*>(
            &swp[(((kq * 3 + 1) << 2) + j4) * 128 + (ud << 2)]);
        wzreg[(j4 << 2) + 0] = zv.x; wzreg[(j4 << 2) + 1] = zv.y;
        wzreg[(j4 << 2) + 2] = zv.z; wzreg[(j4 << 2) + 3] = zv.w;
    }
    // this warp's inbound-slice barrier (warps 2b and 2b+1 share barrier b)
    uint32_t mywait = mbar_u32 + (uint32_t)((kq >> 1) << 3);
    // lane-0 of even warps arms barrier kq>>1 after its wait
    bool armer = ((tid & 63) == 0);

    // ---- gate role ----
    int ug = tid >> 2, bp = tid & 3;
    int ugx = (crank << 5) + ug;
    int b0 = (bg << 3) + (bp << 1), b1 = b0 + 1;
    float br = 0.f, bz = 0.f, bn2 = 0.f;
    int qm10 = -2, qm11 = -2;
    const float* xgb0 = nullptr;
    const float* xgb1 = nullptr;
    if (tid < 128) {
        br = bhh[ugx]; bz = bhh[256 + ugx]; bn2 = bhh[512 + ugx];
        if (gru == 0) { qm10 = qlen[b0] - 1; qm11 = qlen[b1] - 1; }
        xgb0 = xg + (size_t)b0 * T * G3;
        xgb1 = xg + (size_t)b1 * T * G3;
    }

    // bulk-copy role (tid<8): remote dst + remote barrier mbar[crank] on rank tid
    uint32_t dstA = 0, dstB = 0, rmbar = 0;
    if (tid < 8) {
        uint32_t l0 = shT_u32 + 8192u + (uint32_t)(crank << 10);  // p=0 -> buf1
        uint32_t l1 = shT_u32 + (uint32_t)(crank << 10);          // p=1 -> buf0
        uint32_t lm = mbar_u32 + (uint32_t)(crank << 3);
        asm("mapa.shared::cluster.u32 %0, %1, %2;" : "=r"(dstA)  : "r"(l0), "r"(tid));
        asm("mapa.shared::cluster.u32 %0, %1, %2;" : "=r"(dstB)  : "r"(l1), "r"(tid));
        asm("mapa.shared::cluster.u32 %0, %1, %2;" : "=r"(rmbar) : "r"(lm), "r"(tid));
    }

    int redbase_st = ud * RED_USTR + kq;

    for (int step = 0; step < T; step++) {
        int t = (gru == 2) ? (T - 1 - step) : step;
        int p = step & 1;
        int ps = step & 3;          // stg write slot
        int pprev = (step - 1) & 3; // stg slot holding h_{step-1}

        // gate-role x prefetch (no h-slice dependency — issue before any wait)
        float ir0 = 0.f, iz0 = 0.f, in0 = 0.f, hold0 = 0.f;
        float ir1 = 0.f, iz1 = 0.f, in1 = 0.f, hold1 = 0.f;
        if (tid < 128) {
            const float* xr0 = xgb0 + (size_t)t * G3;
            const float* xr1 = xgb1 + (size_t)t * G3;
            ir0 = xr0[ugx]; iz0 = xr0[256 + ugx]; in0 = xr0[512 + ugx];
            ir1 = xr1[ugx]; iz1 = xr1[256 + ugx]; in1 = xr1[512 + ugx];
            hold0 = stg[(pprev << 8) + (ug << 3) + (bp << 1)];
            hold1 = stg[(pprev << 8) + (ug << 3) + (bp << 1) + 1];
        }

        // per-warp wait for the one slice this warp needs; then re-arm that
        // barrier for this step's credits (safe: its previous phase just completed)
        if (step > 0) {
            mbar_wait_cluster(mywait, (uint32_t)((step - 1) & 1));
            if (armer) {
                asm volatile("mbarrier.arrive.expect_tx.shared.b64 _, [%0], %1;"
                             :: "r"(mywait), "r"(1024) : "memory");
            }
        }

        // ---- dot: 3 gates x 16 k x 8 batches per thread ----
        unsigned long long acc[3][4];
#pragma unroll
        for (int g = 0; g < 3; g++)
#pragma unroll
            for (int b = 0; b < 4; b++) acc[g][b] = 0ull;

        const float* hT = shT + ((p << 8) + (kq << 4)) * 8;
#pragma unroll
        for (int j4 = 0; j4 < 4; j4++) {
            ulonglong2 h01[4], h45[4];
#pragma unroll
            for (int kk = 0; kk < 4; kk++) {
                const ulonglong2* hr = reinterpret_cast<const ulonglong2*>(
                    hT + ((j4 << 2) + kk) * 8);
                h01[kk] = hr[0];
                h45[kk] = hr[1];
            }
#pragma unroll
            for (int kk = 0; kk < 4; kk++) {
                unsigned long long wd; DUP2(wd, wrreg[(j4 << 2) + kk]);
                FFMA2(acc[0][0], wd, h01[kk].x);
                FFMA2(acc[0][1], wd, h01[kk].y);
                FFMA2(acc[0][2], wd, h45[kk].x);
                FFMA2(acc[0][3], wd, h45[kk].y);
            }
#pragma unroll
            for (int kk = 0; kk < 4; kk++) {
                unsigned long long wd; DUP2(wd, wzreg[(j4 << 2) + kk]);
                FFMA2(acc[1][0], wd, h01[kk].x);
                FFMA2(acc[1][1], wd, h01[kk].y);
                FFMA2(acc[1][2], wd, h45[kk].x);
                FFMA2(acc[1][3], wd, h45[kk].y);
            }
            {
                float4 wv = *reinterpret_cast<const float4*>(
                    &swp[(((kq * 3 + 2) << 2) + j4) * 128 + (ud << 2)]);
                float wf[4] = {wv.x, wv.y, wv.z, wv.w};
#pragma unroll
                for (int kk = 0; kk < 4; kk++) {
                    unsigned long long wd; DUP2(wd, wf[kk]);
                    FFMA2(acc[2][0], wd, h01[kk].x);
                    FFMA2(acc[2][1], wd, h01[kk].y);
                    FFMA2(acc[2][2], wd, h45[kk].x);
                    FFMA2(acc[2][3], wd, h45[kk].y);
                }
            }
        }
#pragma unroll
        for (int g = 0; g < 3; g++)
#pragma unroll
            for (int b = 0; b < 4; b++)
                redv[redbase_st + ((g << 2) + b) * RED_GSTR] = acc[g][b];
        __syncthreads();

        // ---- merged reduce + gates: 128 threads, 2 batches each ----
        if (tid < 128) {
            unsigned long long s[3];
#pragma unroll
            for (int g = 0; g < 3; g++) {
                const unsigned long long* rp =
                    redv + ug * RED_USTR + ((g << 2) + bp) * RED_GSTR;
                unsigned long long s0 = rp[0], s1 = rp[1], s2 = rp[2], s3 = rp[3];
                ADDF2(s0, s0, rp[4]);  ADDF2(s1, s1, rp[5]);
                ADDF2(s2, s2, rp[6]);  ADDF2(s3, s3, rp[7]);
                ADDF2(s0, s0, rp[8]);  ADDF2(s1, s1, rp[9]);
                ADDF2(s0, s0, rp[12]); ADDF2(s1, s1, rp[13]);
                ADDF2(s2, s2, rp[10]); ADDF2(s3, s3, rp[11]);
                ADDF2(s2, s2, rp[14]); ADDF2(s3, s3, rp[15]);
                ADDF2(s0, s0, s1); ADDF2(s2, s2, s3);
                ADDF2(s0, s0, s2);
                s[g] = s0;
            }
            float ghr0, ghr1, ghz0, ghz1, ghn0, ghn1;
            unpack2(s[0], ghr0, ghr1);
            unpack2(s[1], ghz0, ghz1);
            unpack2(s[2], ghn0, ghn1);

            float r0 = fast_sigmoid(ir0 + ghr0 + br);
            float z0 = fast_sigmoid(iz0 + ghz0 + bz);
            float n0 = fast_tanh(in0 + r0 * (ghn0 + bn2));
            float hnew0 = (1.f - z0) * n0 + z0 * hold0;
            float r1 = fast_sigmoid(ir1 + ghr1 + br);
            float z1 = fast_sigmoid(iz1 + ghz1 + bz);
            float n1 = fast_tanh(in1 + r1 * (ghn1 + bn2));
            float hnew1 = (1.f - z1) * n1 + z1 * hold1;

            stg[(ps << 8) + (ug << 3) + (bp << 1)]     = hnew0;
            stg[(ps << 8) + (ug << 3) + (bp << 1) + 1] = hnew1;
            if (gru == 0) {
                if (t == qm10) d_out[(size_t)b0 * Hv + ugx] = hnew0;
                if (t == qm11) d_out[(size_t)b1 * Hv + ugx] = hnew1;
            } else {
                hout[((size_t)b0 * Sv + t) * Hv + ugx] = hnew0;
                hout[((size_t)b1 * Sv + t) * Hv + ugx] = hnew1;
            }
        }
        __syncthreads();

        // ---- broadcast: 8 async 1KB bulk copies crediting peers' mbar[crank] ----
        if (tid < 8) {
            asm volatile("fence.proxy.async.shared::cta;" ::: "memory");
            uint32_t dst = p ? dstB : dstA;
            uint32_t src = stg_u32 + (uint32_t)(ps << 10);
            asm volatile(
                "cp.async.bulk.shared::cluster.shared::cta.mbarrier::complete_tx::bytes "
                "[%0], [%1], %2, [%3];"
                :: "r"(dst), "r"(src), "r"(1024), "r"(rmbar) : "memory");
        }
        // NOTE: no end-of-step wait — consumed per-warp at top of next step
    }

    // ---- drain: sender source-read completion + final inbound delivery ----
    if (tid < 8) {
        asm volatile("cp.async.bulk.commit_group;" ::: "memory");
        asm volatile("cp.async.bulk.wait_group 0;" ::: "memory");
        mbar_wait_cluster(mbar_u32 + tid * 8, (uint32_t)((T - 1) & 1));
    }
    __syncthreads();
    asm volatile("barrier.cluster.arrive.aligned;" ::: "memory");
    asm volatile("barrier.cluster.wait.aligned;"   ::: "memory");
}

// ---------------- combine: f_out = hf + hb, plus num_facts ----------------
__global__ void combine_kernel(const int* __restrict__ slen, float* __restrict__ d_out) {
    int idx = blockIdx.x * blockDim.x + threadIdx.x;
    const int NF4 = (Bv * Sv * Hv) / 4;
    if (idx < NF4) {
        const float4* hf4 = reinterpret_cast<const float4*>(g_hf);
        const float4* hb4 = reinterpret_cast<const float4*>(g_hb);
        float4 a = hf4[idx], c = hb4[idx];
        float4 o = make_float4(a.x + c.x, a.y + c.y, a.z + c.z, a.w + c.w);
        reinterpret_cast<float4*>(d_out + Bv * Hv)[idx] = o;
    }
    if (idx < Bv) {
        int c = 0;
        const int* sl = slen + idx * Sv;
        for (int s = 0; s < Sv; s++) c += (sl[s] > 0) ? 1 : 0;
        d_out[Bv * Hv + Bv * Sv * Hv + idx] = (float)c;
    }
}

// ---------------- launch ----------------
extern "C" void kernel_launch(void* const* d_in, const int* in_sizes, int n_in,
                              void* d_out, int out_size) {
    const int*   queries = (const int*)d_in[0];
    const int*   qlen    = (const int*)d_in[1];
    const int*   docs    = (const int*)d_in[2];
    const int*   slen    = (const int*)d_in[3];
    const float* emb     = (const float*)d_in[4];
    const float* q_wih   = (const float*)d_in[5];
    const float* q_whh   = (const float*)d_in[6];
    const float* q_bih   = (const float*)d_in[7];
    const float* q_bhh   = (const float*)d_in[8];
    const float* f_wih   = (const float*)d_in[9];
    const float* f_whh   = (const float*)d_in[10];
    const float* f_bih   = (const float*)d_in[11];
    const float* f_bhh   = (const float*)d_in[12];
    const float* b_wih   = (const float*)d_in[13];
    const float* b_whh   = (const float*)d_in[14];
    const float* b_bih   = (const float*)d_in[15];
    const float* b_bhh   = (const float*)d_in[16];
    float* out = (float*)d_out;

    // floats: swp 24576 + shT 4096 + redv 13120 + stg 1024, + 8 mbars + pad
    const int GRU_SMEM = (24576 + 4096 + 32 * RED_USTR * 2 + 1024) * 4 + 96;
    cudaFuncSetAttribute(gru_cluster, cudaFuncAttributeMaxDynamicSharedMemorySize, GRU_SMEM);

    facts_kernel<<<Bv * Sv, 320>>>(docs, slen, emb);

    dim3 gg(6, 20);
    xg_gemm<<<gg, 512>>>(queries, emb, q_wih, f_wih, b_wih, q_bih, f_bih, b_bih);

    gru_cluster<<<96, 512, GRU_SMEM>>>(qlen, q_whh, f_whh, b_whh,
                                       q_bhh, f_bhh, b_bhh, out);

    combine_kernel<<<(Bv * Sv * Hv / 4 + 255) / 256, 256>>>(slen, out);
}

// round 12
// speedup vs baseline: 1.4580x; 1.0823x over previous
#include <cuda_runtime.h>
#include <math.h>
#include <stdint.h>

#define Bv   32
#define QL   32
#define DOCL 2048
#define Sv   64
#define Ev   300
#define Hv   256
#define G3   768    // 3*H
#define KP   304    // padded K for GEMM
#define CLS  8      // cluster size

// ---------------- scratch ----------------
__device__ float g_facts[Bv*Sv*Ev];
__device__ float g_xg_q[Bv*QL*G3];
__device__ float g_xg_f[Bv*Sv*G3];
__device__ float g_xg_b[Bv*Sv*G3];

// packed 2xfp32 ops
#define FFMA2(acc, a, b) asm("fma.rn.f32x2 %0, %1, %2, %0;" : "+l"(acc) : "l"(a), "l"(b))
#define ADDF2(o, a, b)   asm("add.rn.f32x2 %0, %1, %2;" : "=l"(o) : "l"(a), "l"(b))
#define DUP2(d, s)       asm("mov.b64 %0, {%1, %1};" : "=l"(d) : "f"(s))

__device__ __forceinline__ void unpack2(unsigned long long v, float& lo, float& hi) {
    asm("mov.b64 {%0,%1}, %2;" : "=f"(lo), "=f"(hi) : "l"(v));
}
__device__ __forceinline__ float fast_sigmoid(float x) {
    return 1.f / (1.f + __expf(-x));
}
__device__ __forceinline__ float fast_tanh(float x) {
    return 2.f / (1.f + __expf(-2.f * x)) - 1.f;
}
__device__ __forceinline__ void mbar_wait_cluster(uint32_t mbar, uint32_t parity) {
    asm volatile(
        "{\n\t"
        ".reg .pred P;\n\t"
        "MWL_%=:\n\t"
        "mbarrier.try_wait.parity.acquire.cluster.shared::cta.b64 P, [%0], %1, 0x989680;\n\t"
        "@!P bra MWL_%=;\n\t"
        "}" :: "r"(mbar), "r"(parity) : "memory");
}

// ---------------- facts: ragged mean pooling + f_out zero + num_facts ----------------
__global__ void facts_kernel(const int* __restrict__ docs,
                             const int* __restrict__ slen,
                             const float* __restrict__ emb,
                             float* __restrict__ d_out) {
    __shared__ int toks[DOCL];
    int bs = blockIdx.x;
    int b = bs >> 6, s = bs & 63;

    // zero this block's 256-float slice of f_out (for GRU atomicAdd)
    if (threadIdx.x < 64) {
        reinterpret_cast<float4*>(d_out + Bv * Hv)[bs * 64 + threadIdx.x] =
            make_float4(0.f, 0.f, 0.f, 0.f);
    }
    // num_facts for batch b (one block per batch does it)
    if (s == 0 && threadIdx.x == 300) {
        int c = 0;
        const int* sl = slen + b * Sv;
        for (int ss = 0; ss < Sv; ss++) c += (sl[ss] > 0) ? 1 : 0;
        d_out[Bv * Hv + Bv * Sv * Hv + b] = (float)c;
    }

    const int* sl = slen + b * Sv;
    int start = 0;
    for (int i = 0; i < s; i++) start += sl[i];
    int len = sl[s];
    if (len > DOCL - start) len = DOCL - start;
    const int* dp = docs + b * DOCL + start;
    for (int i = threadIdx.x; i < len; i += blockDim.x) toks[i] = dp[i];
    __syncthreads();
    int e = threadIdx.x;
    if (e < Ev) {
        float a0 = 0.f, a1 = 0.f, a2 = 0.f, a3 = 0.f;
        int i = 0;
        for (; i + 4 <= len; i += 4) {
            a0 += emb[(size_t)toks[i]     * Ev + e];
            a1 += emb[(size_t)toks[i + 1] * Ev + e];
            a2 += emb[(size_t)toks[i + 2] * Ev + e];
            a3 += emb[(size_t)toks[i + 3] * Ev + e];
        }
        for (; i < len; i++) a0 += emb[(size_t)toks[i] * Ev + e];
        float acc = (a0 + a1) + (a2 + a3);
        float d = (len > 0) ? (float)len : 1.0f;
        g_facts[(size_t)bs * Ev + e] = acc / d;
    }
}

// ---------------- merged xg GEMM: 5120 x 768 x 304 (unchanged) ----------------
__global__ __launch_bounds__(512, 1) void xg_gemm(
        const int* __restrict__ queries, const float* __restrict__ emb,
        const float* __restrict__ qwih, const float* __restrict__ fwih,
        const float* __restrict__ bwih,
        const float* __restrict__ qbih, const float* __restrict__ fbih,
        const float* __restrict__ bbih) {
    __shared__ float As[16][264];
    __shared__ float Bs[16][132];

    int m0 = blockIdx.y * 256, n0 = blockIdx.x * 128;
    int which = (m0 < 1024) ? 0 : ((m0 < 3072) ? 1 : 2);
    int mbase = (which == 0) ? 0 : (which == 1) ? 1024 : 3072;
    const float* wih = (which == 0) ? qwih : (which == 1) ? fwih : bwih;
    const float* bih = (which == 0) ? qbih : (which == 1) ? fbih : bbih;
    float* outb = ((which == 0) ? g_xg_q : (which == 1) ? g_xg_f : g_xg_b)
                  + (size_t)(m0 - mbase) * G3;

    int tid = threadIdx.x, tx = tid & 15, ty = tid >> 4;

    const float* asrc[2];
    int ac[2];
#pragma unroll
    for (int i = 0; i < 2; i++) {
        int idx = tid + i * 512;
        int r = idx >> 2;
        ac[i] = idx & 3;
        int m = m0 + r;
        asrc[i] = (which == 0) ? (emb + (size_t)queries[m] * Ev)
                               : (g_facts + (size_t)(m - mbase) * Ev);
    }
    int ar0 = (tid) >> 2, ar1 = (tid + 512) >> 2;
    int bn = tid >> 2, bkq = tid & 3;
    const float* brow = wih + (size_t)(n0 + bn) * Ev;

    unsigned long long acc[8][4];
#pragma unroll
    for (int i = 0; i < 8; i++)
#pragma unroll
        for (int j = 0; j < 4; j++) acc[i][j] = 0ull;

    for (int k0 = 0; k0 < KP; k0 += 16) {
#pragma unroll
        for (int i = 0; i < 2; i++) {
            int k = k0 + ac[i] * 4;
            float4 av = (k < Ev) ? *reinterpret_cast<const float4*>(asrc[i] + k)
                                 : make_float4(0.f, 0.f, 0.f, 0.f);
            int r = (i == 0) ? ar0 : ar1;
            As[ac[i]*4+0][r] = av.x; As[ac[i]*4+1][r] = av.y;
            As[ac[i]*4+2][r] = av.z; As[ac[i]*4+3][r] = av.w;
        }
        {
            int k = k0 + bkq * 4;
            float4 bv = (k < Ev) ? *reinterpret_cast<const float4*>(brow + k)
                                 : make_float4(0.f, 0.f, 0.f, 0.f);
            Bs[bkq*4+0][bn] = bv.x; Bs[bkq*4+1][bn] = bv.y;
            Bs[bkq*4+2][bn] = bv.z; Bs[bkq*4+3][bn] = bv.w;
        }
        __syncthreads();
#pragma unroll
        for (int k = 0; k < 16; k++) {
            float4 a0 = *reinterpret_cast<const float4*>(&As[k][ty * 8]);
            float4 a1 = *reinterpret_cast<const float4*>(&As[k][ty * 8 + 4]);
            ulonglong2 b01 = *reinterpret_cast<const ulonglong2*>(&Bs[k][tx * 8]);
            ulonglong2 b23 = *reinterpret_cast<const ulonglong2*>(&Bs[k][tx * 8 + 4]);
            float af[8] = {a0.x, a0.y, a0.z, a0.w, a1.x, a1.y, a1.z, a1.w};
#pragma unroll
            for (int i = 0; i < 8; i++) {
                unsigned long long ad; DUP2(ad, af[i]);
                FFMA2(acc[i][0], ad, b01.x);
                FFMA2(acc[i][1], ad, b01.y);
                FFMA2(acc[i][2], ad, b23.x);
                FFMA2(acc[i][3], ad, b23.y);
            }
        }
        __syncthreads();
    }
#pragma unroll
    for (int i = 0; i < 8; i++) {
        float* orow = outb + (size_t)(ty * 8 + i) * G3 + n0 + tx * 8;
#pragma unroll
        for (int jp = 0; jp < 4; jp++) {
            float lo, hi; unpack2(acc[i][jp], lo, hi);
            orow[2*jp]   = lo + bih[n0 + tx*8 + 2*jp];
            orow[2*jp+1] = hi + bih[n0 + tx*8 + 2*jp + 1];
        }
    }
}

// ---------------- GRU: decoupled gate warps, double-buffered partials ----------------
// 12 clusters x 8 CTAs x 512 threads.
// Dot role:  ud = tid&31, kq = tid>>5 (16 k each); warp kq waits only rank kq>>1's slice.
// Gate role: tid<256: ug = tid>>3, bl = tid&7 (1 batch each); bar.sync 1,256 scopes
//            the gates->broadcast ordering to warps 0-7 so warps 8-15 run ahead.
#define RED_USTR 205
#define RED_GSTR 17
#define REDBUF  (32 * RED_USTR)   // u64 per parity buffer
extern "C" __global__ void __cluster_dims__(CLS, 1, 1) __launch_bounds__(512, 1)
gru_cluster(const int* __restrict__ qlen,
            const float* __restrict__ qwhh, const float* __restrict__ fwhh,
            const float* __restrict__ bwhh,
            const float* __restrict__ qbhh, const float* __restrict__ fbhh,
            const float* __restrict__ bbhh,
            float* __restrict__ d_out) {
    extern __shared__ float sm[];
    float* swp = sm;                                         // 24576 floats
    float* shT = sm + 24576;                                 // 4096 floats [2][256][8]
    unsigned long long* redv = (unsigned long long*)(sm + 24576 + 4096);  // 2 x REDBUF
    float* stg = (float*)(redv + 2 * REDBUF);                // [4][256]
    unsigned long long* mbar = (unsigned long long*)(stg + 1024);  // [8]

    int cid = blockIdx.x / CLS;
    int crank = blockIdx.x - cid * CLS;
    int gru = cid >> 2, bg = cid & 3;
    int tid = threadIdx.x;

    const float* whh = (gru == 0) ? qwhh : (gru == 1) ? fwhh : bwhh;
    const float* bhh = (gru == 0) ? qbhh : (gru == 1) ? fbhh : bbhh;
    const float* xg  = (gru == 0) ? g_xg_q : (gru == 1) ? g_xg_f : g_xg_b;
    float* fout = d_out + Bv * Hv;
    int T = (gru == 0) ? QL : Sv;

    uint32_t shT_u32, mbar_u32, stg_u32;
    asm("{ .reg .u64 t; cvta.to.shared.u64 t, %1; cvt.u32.u64 %0, t; }"
        : "=r"(shT_u32) : "l"(shT));
    asm("{ .reg .u64 t; cvta.to.shared.u64 t, %1; cvt.u32.u64 %0, t; }"
        : "=r"(mbar_u32) : "l"(mbar));
    asm("{ .reg .u64 t; cvta.to.shared.u64 t, %1; cvt.u32.u64 %0, t; }"
        : "=r"(stg_u32) : "l"(stg));

    // ---- init: repack weights; zero h + stg; init 8 mbarriers; arm phase 0 ----
    for (int i = tid; i < 96 * 64; i += 512) {
        int gi = i >> 6, k4 = i & 63;
        int g = gi >> 5, u = gi & 31;
        float4 v = *reinterpret_cast<const float4*>(
            &whh[(size_t)((g << 8) + (crank << 5) + u) * Hv + (k4 << 2)]);
        int kq = k4 >> 2, j4 = k4 & 3;
        *reinterpret_cast<float4*>(&swp[(((kq * 3 + g) << 2) + j4) * 128 + (u << 2)]) = v;
    }
    for (int i = tid; i < 4096; i += 512) shT[i] = 0.f;
    for (int i = tid; i < 1024; i += 512) stg[i] = 0.f;
    if (tid < 8) {
        asm volatile("mbarrier.init.shared.b64 [%0], %1;"
                     :: "r"(mbar_u32 + tid * 8), "r"(1) : "memory");
        asm volatile("mbarrier.arrive.expect_tx.shared.b64 _, [%0], %1;"
                     :: "r"(mbar_u32 + tid * 8), "r"(1024) : "memory");
    }
    __syncthreads();
    asm volatile("barrier.cluster.arrive.aligned;" ::: "memory");
    asm volatile("barrier.cluster.wait.aligned;"   ::: "memory");

    // ---- dot role: r and z gate weights in registers ----
    int ud = tid & 31, kq = tid >> 5;
    float wrreg[16], wzreg[16];
#pragma unroll
    for (int j4 = 0; j4 < 4; j4++) {
        float4 wv = *reinterpret_cast<const float4*>(
            &swp[(((kq * 3 + 0) << 2) + j4) * 128 + (ud << 2)]);
        wrreg[(j4 << 2) + 0] = wv.x; wrreg[(j4 << 2) + 1] = wv.y;
        wrreg[(j4 << 2) + 2] = wv.z; wrreg[(j4 << 2) + 3] = wv.w;
        float4 zv = *reinterpret_cast<const float4*>(
            &swp[(((kq * 3 + 1) << 2) + j4) * 128 + (ud << 2)]);
        wzreg[(j4 << 2) + 0] = zv.x; wzreg[(j4 << 2) + 1] = zv.y;
        wzreg[(j4 << 2) + 2] = zv.z; wzreg[(j4 << 2) + 3] = zv.w;
    }
    uint32_t mywait = mbar_u32 + (uint32_t)((kq >> 1) << 3);
    bool armer = ((tid & 63) == 0);

    // ---- gate role: tid<256, 1 batch each ----
    int ug = tid >> 3, bl = tid & 7;
    int ugx = (crank << 5) + ug;
    int bgl = (bg << 3) + bl;
    float br = 0.f, bz = 0.f, bn2 = 0.f;
    int qm1 = -2;
    const float* xgb = nullptr;
    if (tid < 256) {
        br = bhh[ugx]; bz = bhh[256 + ugx]; bn2 = bhh[512 + ugx];
        if (gru == 0) qm1 = qlen[bgl] - 1;
        xgb = xg + (size_t)bgl * T * G3;
    }

    // bulk-copy role (tid<8)
    uint32_t dstA = 0, dstB = 0, rmbar = 0;
    if (tid < 8) {
        uint32_t l0 = shT_u32 + 8192u + (uint32_t)(crank << 10);  // p=0 -> buf1
        uint32_t l1 = shT_u32 + (uint32_t)(crank << 10);          // p=1 -> buf0
        uint32_t lm = mbar_u32 + (uint32_t)(crank << 3);
        asm("mapa.shared::cluster.u32 %0, %1, %2;" : "=r"(dstA)  : "r"(l0), "r"(tid));
        asm("mapa.shared::cluster.u32 %0, %1, %2;" : "=r"(dstB)  : "r"(l1), "r"(tid));
        asm("mapa.shared::cluster.u32 %0, %1, %2;" : "=r"(rmbar) : "r"(lm), "r"(tid));
    }

    int redbase_st = ud * RED_USTR + kq;

    for (int step = 0; step < T; step++) {
        int t = (gru == 2) ? (T - 1 - step) : step;
        int p = step & 1;
        int ps = step & 3;
        int pprev = (step - 1) & 3;
        unsigned long long* redq = redv + (size_t)(step & 1) * REDBUF;

        // gate-role x prefetch (independent of h slices)
        float ir = 0.f, iz = 0.f, in_ = 0.f, hold = 0.f;
        if (tid < 256) {
            const float* xr = xgb + (size_t)t * G3;
            ir = xr[ugx]; iz = xr[256 + ugx]; in_ = xr[512 + ugx];
            hold = stg[(pprev << 8) + (ug << 3) + bl];
        }

        // per-warp wait for the one needed slice, then re-arm that barrier
        if (step > 0) {
            mbar_wait_cluster(mywait, (uint32_t)((step - 1) & 1));
            if (armer) {
                asm volatile("mbarrier.arrive.expect_tx.shared.b64 _, [%0], %1;"
                             :: "r"(mywait), "r"(1024) : "memory");
            }
        }

        // ---- dot: 3 gates x 16 k x 8 batches per thread ----
        unsigned long long acc[3][4];
#pragma unroll
        for (int g = 0; g < 3; g++)
#pragma unroll
            for (int b = 0; b < 4; b++) acc[g][b] = 0ull;

        const float* hT = shT + ((p << 8) + (kq << 4)) * 8;
#pragma unroll
        for (int j4 = 0; j4 < 4; j4++) {
            ulonglong2 h01[4], h45[4];
#pragma unroll
            for (int kk = 0; kk < 4; kk++) {
                const ulonglong2* hr = reinterpret_cast<const ulonglong2*>(
                    hT + ((j4 << 2) + kk) * 8);
                h01[kk] = hr[0];
                h45[kk] = hr[1];
            }
#pragma unroll
            for (int kk = 0; kk < 4; kk++) {
                unsigned long long wd; DUP2(wd, wrreg[(j4 << 2) + kk]);
                FFMA2(acc[0][0], wd, h01[kk].x);
                FFMA2(acc[0][1], wd, h01[kk].y);
                FFMA2(acc[0][2], wd, h45[kk].x);
                FFMA2(acc[0][3], wd, h45[kk].y);
            }
#pragma unroll
            for (int kk = 0; kk < 4; kk++) {
                unsigned long long wd; DUP2(wd, wzreg[(j4 << 2) + kk]);
                FFMA2(acc[1][0], wd, h01[kk].x);
                FFMA2(acc[1][1], wd, h01[kk].y);
                FFMA2(acc[1][2], wd, h45[kk].x);
                FFMA2(acc[1][3], wd, h45[kk].y);
            }
            {
                float4 wv = *reinterpret_cast<const float4*>(
                    &swp[(((kq * 3 + 2) << 2) + j4) * 128 + (ud << 2)]);
                float wf[4] = {wv.x, wv.y, wv.z, wv.w};
#pragma unroll
                for (int kk = 0; kk < 4; kk++) {
                    unsigned long long wd; DUP2(wd, wf[kk]);
                    FFMA2(acc[2][0], wd, h01[kk].x);
                    FFMA2(acc[2][1], wd, h01[kk].y);
                    FFMA2(acc[2][2], wd, h45[kk].x);
                    FFMA2(acc[2][3], wd, h45[kk].y);
                }
            }
        }
#pragma unroll
        for (int g = 0; g < 3; g++)
#pragma unroll
            for (int b = 0; b < 4; b++)
                redq[redbase_st + ((g << 2) + b) * RED_GSTR] = acc[g][b];
        __syncthreads();   // redv(parity) all-to-all visibility

        // ---- gate warps only: reduce + gates + broadcast; others run ahead ----
        if (tid < 256) {
            unsigned long long s[3];
#pragma unroll
            for (int g = 0; g < 3; g++) {
                const unsigned long long* rp =
                    redq + ug * RED_USTR + ((g << 2) + (bl >> 1)) * RED_GSTR;
                unsigned long long s0 = rp[0], s1 = rp[1], s2 = rp[2], s3 = rp[3];
                ADDF2(s0, s0, rp[4]);  ADDF2(s1, s1, rp[5]);
                ADDF2(s2, s2, rp[6]);  ADDF2(s3, s3, rp[7]);
                ADDF2(s0, s0, rp[8]);  ADDF2(s1, s1, rp[9]);
                ADDF2(s0, s0, rp[12]); ADDF2(s1, s1, rp[13]);
                ADDF2(s2, s2, rp[10]); ADDF2(s3, s3, rp[11]);
                ADDF2(s2, s2, rp[14]); ADDF2(s3, s3, rp[15]);
                ADDF2(s0, s0, s1); ADDF2(s2, s2, s3);
                ADDF2(s0, s0, s2);
                s[g] = s0;
            }
            float lo, hi;
            unpack2(s[0], lo, hi); float ghr = (bl & 1) ? hi : lo;
            unpack2(s[1], lo, hi); float ghz = (bl & 1) ? hi : lo;
            unpack2(s[2], lo, hi); float ghn = (bl & 1) ? hi : lo;

            float r = fast_sigmoid(ir + ghr + br);
            float z = fast_sigmoid(iz + ghz + bz);
            float n = fast_tanh(in_ + r * (ghn + bn2));
            float hnew = (1.f - z) * n + z * hold;

            stg[(ps << 8) + (ug << 3) + bl] = hnew;
            asm volatile("bar.sync 1, 256;" ::: "memory");

            // broadcast: 8 async 1KB bulk copies crediting peers' mbar[crank]
            if (tid < 8) {
                asm volatile("fence.proxy.async.shared::cta;" ::: "memory");
                uint32_t dst = p ? dstB : dstA;
                uint32_t src = stg_u32 + (uint32_t)(ps << 10);
                asm volatile(
                    "cp.async.bulk.shared::cluster.shared::cta.mbarrier::complete_tx::bytes "
                    "[%0], [%1], %2, [%3];"
                    :: "r"(dst), "r"(src), "r"(1024), "r"(rmbar) : "memory");
            }
            // gmem output overlaps the in-flight broadcast
            if (gru == 0) {
                if (t == qm1) d_out[(size_t)bgl * Hv + ugx] = hnew;
            } else {
                atomicAdd(&fout[((size_t)bgl * Sv + t) * Hv + ugx], hnew);
            }
        }
    }

    // ---- drain ----
    if (tid < 8) {
        asm volatile("cp.async.bulk.commit_group;" ::: "memory");
        asm volatile("cp.async.bulk.wait_group 0;" ::: "memory");
        mbar_wait_cluster(mbar_u32 + tid * 8, (uint32_t)((T - 1) & 1));
    }
    __syncthreads();
    asm volatile("barrier.cluster.arrive.aligned;" ::: "memory");
    asm volatile("barrier.cluster.wait.aligned;"   ::: "memory");
}

// ---------------- launch ----------------
extern "C" void kernel_launch(void* const* d_in, const int* in_sizes, int n_in,
                              void* d_out, int out_size) {
    const int*   queries = (const int*)d_in[0];
    const int*   qlen    = (const int*)d_in[1];
    const int*   docs    = (const int*)d_in[2];
    const int*   slen    = (const int*)d_in[3];
    const float* emb     = (const float*)d_in[4];
    const float* q_wih   = (const float*)d_in[5];
    const float* q_whh   = (const float*)d_in[6];
    const float* q_bih   = (const float*)d_in[7];
    const float* q_bhh   = (const float*)d_in[8];
    const float* f_wih   = (const float*)d_in[9];
    const float* f_whh   = (const float*)d_in[10];
    const float* f_bih   = (const float*)d_in[11];
    const float* f_bhh   = (const float*)d_in[12];
    const float* b_wih   = (const float*)d_in[13];
    const float* b_whh   = (const float*)d_in[14];
    const float* b_bih   = (const float*)d_in[15];
    const float* b_bhh   = (const float*)d_in[16];
    float* out = (float*)d_out;

    // bytes: swp 98304 + shT 16384 + redv 104960 + stg 4096 + mbars/pad 96
    const int GRU_SMEM = 24576 * 4 + 4096 * 4 + 2 * REDBUF * 8 + 1024 * 4 + 96;
    cudaFuncSetAttribute(gru_cluster, cudaFuncAttributeMaxDynamicSharedMemorySize, GRU_SMEM);

    facts_kernel<<<Bv * Sv, 320>>>(docs, slen, emb, out);

    dim3 gg(6, 20);
    xg_gemm<<<gg, 512>>>(queries, emb, q_wih, f_wih, b_wih, q_bih, f_bih, b_bih);

    gru_cluster<<<96, 512, GRU_SMEM>>>(qlen, q_whh, f_whh, b_whh,
                                       q_bhh, f_bhh, b_bhh, out);
}